// round 2
// baseline (speedup 1.0000x reference)
#include <cuda_runtime.h>
#include <math.h>

#define T 2048      // tokens = SEQ*BS
#define DM 2048     // model dim
#define FF 2048     // ffn dim
#define NE 8        // experts

// ---------------- scratch (device globals; no allocation allowed) ----------------
__device__ __align__(16) float g_xs[(size_t)T * DM];   // score-scaled tokens
__device__ __align__(16) float g_h [(size_t)T * FF];   // routed SwiGLU intermediate (permuted rows)
__device__ __align__(16) float g_hs[(size_t)T * FF];   // shared SwiGLU intermediate (token rows)
__device__ int g_eidx[T];
__device__ int g_counts[NE];
__device__ int g_offsets[NE];
__device__ int g_cursor[NE];
__device__ int g_perm[T];

// ---------------- init ----------------
__global__ void init_kernel() {
    if (threadIdx.x < NE) g_counts[threadIdx.x] = 0;
}

// ---------------- router: logits, top-1, sigmoid score, scale tokens ----------------
__global__ void __launch_bounds__(256) router_kernel(const float* __restrict__ x,
                                                     const float* __restrict__ rw) {
    int t = blockIdx.x;
    const float* xr = x + (size_t)t * DM;
    float acc[NE];
#pragma unroll
    for (int e = 0; e < NE; e++) acc[e] = 0.f;
    for (int d = threadIdx.x; d < DM; d += 256) {
        float xv = xr[d];
        const float* r = rw + (size_t)d * NE;
#pragma unroll
        for (int e = 0; e < NE; e++) acc[e] = fmaf(xv, r[e], acc[e]);
    }
    __shared__ float sacc[8][NE];
    __shared__ float s_score;
    int lane = threadIdx.x & 31, warp = threadIdx.x >> 5;
#pragma unroll
    for (int e = 0; e < NE; e++) {
        float v = acc[e];
#pragma unroll
        for (int o = 16; o > 0; o >>= 1) v += __shfl_down_sync(0xffffffffu, v, o);
        if (lane == 0) sacc[warp][e] = v;
    }
    __syncthreads();
    if (threadIdx.x == 0) {
        float best = -INFINITY; int bi = 0;
#pragma unroll
        for (int e = 0; e < NE; e++) {
            float v = 0.f;
#pragma unroll
            for (int w = 0; w < 8; w++) v += sacc[w][e];
            if (v > best) { best = v; bi = e; }   // strict > keeps first occurrence (argmax semantics)
        }
        s_score = 1.f / (1.f + expf(-best));
        g_eidx[t] = bi;
        atomicAdd(&g_counts[bi], 1);
    }
    __syncthreads();
    float sc = s_score;
    for (int d = threadIdx.x; d < DM; d += 256)
        g_xs[(size_t)t * DM + d] = xr[d] * sc;
}

// ---------------- tiny scan: expert offsets + cursors ----------------
__global__ void scan_kernel() {
    if (threadIdx.x == 0) {
        int off = 0;
        for (int e = 0; e < NE; e++) {
            g_offsets[e] = off;
            g_cursor[e]  = off;
            off += g_counts[e];
        }
    }
}

// ---------------- scatter tokens into per-expert contiguous order ----------------
__global__ void scatter_kernel() {
    int t = blockIdx.x * blockDim.x + threadIdx.x;
    if (t < T) {
        int e = g_eidx[t];
        int pos = atomicAdd(&g_cursor[e], 1);
        g_perm[pos] = t;
    }
}

// ---------------- gate/up GEMM + fused SwiGLU ----------------
// MODE 0: routed  — A rows gathered via g_perm from g_xs, weights per expert (blockIdx.z),
//                   output g_h in permuted order.
// MODE 1: shared  — A = Xext (raw hidden), single weight set, output g_hs token order.
template<int MODE>
__global__ void __launch_bounds__(256) gemm_gateup_kernel(const float* __restrict__ Xext,
                                                          const float* __restrict__ Wg_all,
                                                          const float* __restrict__ Wu_all) {
    int e    = (MODE == 0) ? blockIdx.z : 0;
    int M    = (MODE == 0) ? g_counts[e] : T;
    int base = (MODE == 0) ? g_offsets[e] : 0;
    int m0 = blockIdx.y * 64;
    if (m0 >= M) return;
    int n0 = blockIdx.x * 64;

    const float* A    = (MODE == 0) ? g_xs : Xext;
    float*       Hout = (MODE == 0) ? g_h  : g_hs;
    const float* Wg = Wg_all + (size_t)e * DM * FF;
    const float* Wu = Wu_all + (size_t)e * DM * FF;

    __shared__ __align__(16) float As [16][64];
    __shared__ __align__(16) float Bgs[16][64];
    __shared__ __align__(16) float Bus[16][64];

    int tid = threadIdx.x;
    int am = tid >> 2;            // 0..63 : A tile row (m)
    int ak = (tid & 3) * 4;       // 0,4,8,12 : A k sub-offset
    int row = m0 + am;
    const float* arow = nullptr;
    if (row < M) {
        int tok = (MODE == 0) ? g_perm[base + row] : row;
        arow = A + (size_t)tok * DM;
    }
    int bk = tid >> 4;            // 0..15 : B tile row (k)
    int bn = (tid & 15) * 4;      // B col sub-offset
    int ty = tid >> 4, tx = tid & 15;

    float accg[4][4], accu[4][4];
#pragma unroll
    for (int i = 0; i < 4; i++)
#pragma unroll
        for (int j = 0; j < 4; j++) { accg[i][j] = 0.f; accu[i][j] = 0.f; }

    for (int k0 = 0; k0 < DM; k0 += 16) {
        float4 av = arow ? *(const float4*)(arow + k0 + ak) : make_float4(0.f, 0.f, 0.f, 0.f);
        As[ak + 0][am] = av.x; As[ak + 1][am] = av.y;
        As[ak + 2][am] = av.z; As[ak + 3][am] = av.w;
        *(float4*)&Bgs[bk][bn] = *(const float4*)(Wg + (size_t)(k0 + bk) * FF + n0 + bn);
        *(float4*)&Bus[bk][bn] = *(const float4*)(Wu + (size_t)(k0 + bk) * FF + n0 + bn);
        __syncthreads();
#pragma unroll
        for (int kk = 0; kk < 16; kk++) {
            float4 a  = *(const float4*)&As [kk][ty * 4];
            float4 bg = *(const float4*)&Bgs[kk][tx * 4];
            float4 bu = *(const float4*)&Bus[kk][tx * 4];
            float aa[4]  = {a.x, a.y, a.z, a.w};
            float bgv[4] = {bg.x, bg.y, bg.z, bg.w};
            float buv[4] = {bu.x, bu.y, bu.z, bu.w};
#pragma unroll
            for (int i = 0; i < 4; i++)
#pragma unroll
                for (int j = 0; j < 4; j++) {
                    accg[i][j] = fmaf(aa[i], bgv[j], accg[i][j]);
                    accu[i][j] = fmaf(aa[i], buv[j], accu[i][j]);
                }
        }
        __syncthreads();
    }
#pragma unroll
    for (int i = 0; i < 4; i++) {
        int r = m0 + ty * 4 + i;
        if (r < M) {
            float* o = Hout + (size_t)(base + r) * FF + n0 + tx * 4;
            float h[4];
#pragma unroll
            for (int j = 0; j < 4; j++) {
                float g = accg[i][j];
                float s = 1.f / (1.f + expf(-g));
                h[j] = g * s * accu[i][j];       // silu(g) * u
            }
            *(float4*)o = make_float4(h[0], h[1], h[2], h[3]);
        }
    }
}

// ---------------- down GEMM ----------------
// MODE 0: routed — A = g_h permuted rows, per-expert weights, scatter rows to d_out (overwrite).
// MODE 1: shared — A = g_hs token rows, shared weights, accumulate into d_out.
template<int MODE>
__global__ void __launch_bounds__(256) gemm_down_kernel(const float* __restrict__ W_all,
                                                        float* __restrict__ Out) {
    int e    = (MODE == 0) ? blockIdx.z : 0;
    int M    = (MODE == 0) ? g_counts[e] : T;
    int base = (MODE == 0) ? g_offsets[e] : 0;
    int m0 = blockIdx.y * 64;
    if (m0 >= M) return;
    int n0 = blockIdx.x * 64;

    const float* A = (MODE == 0) ? g_h : g_hs;
    const float* W = W_all + (size_t)e * FF * DM;

    __shared__ __align__(16) float As[16][64];
    __shared__ __align__(16) float Bs[16][64];

    int tid = threadIdx.x;
    int am = tid >> 2;
    int ak = (tid & 3) * 4;
    int row = m0 + am;
    const float* arow = (row < M) ? (A + (size_t)(base + row) * FF) : nullptr;
    int bk = tid >> 4;
    int bn = (tid & 15) * 4;
    int ty = tid >> 4, tx = tid & 15;

    float acc[4][4];
#pragma unroll
    for (int i = 0; i < 4; i++)
#pragma unroll
        for (int j = 0; j < 4; j++) acc[i][j] = 0.f;

    for (int k0 = 0; k0 < FF; k0 += 16) {
        float4 av = arow ? *(const float4*)(arow + k0 + ak) : make_float4(0.f, 0.f, 0.f, 0.f);
        As[ak + 0][am] = av.x; As[ak + 1][am] = av.y;
        As[ak + 2][am] = av.z; As[ak + 3][am] = av.w;
        *(float4*)&Bs[bk][bn] = *(const float4*)(W + (size_t)(k0 + bk) * DM + n0 + bn);
        __syncthreads();
#pragma unroll
        for (int kk = 0; kk < 16; kk++) {
            float4 a = *(const float4*)&As[kk][ty * 4];
            float4 b = *(const float4*)&Bs[kk][tx * 4];
            float aa[4] = {a.x, a.y, a.z, a.w};
            float bb[4] = {b.x, b.y, b.z, b.w};
#pragma unroll
            for (int i = 0; i < 4; i++)
#pragma unroll
                for (int j = 0; j < 4; j++)
                    acc[i][j] = fmaf(aa[i], bb[j], acc[i][j]);
        }
        __syncthreads();
    }
#pragma unroll
    for (int i = 0; i < 4; i++) {
        int r = m0 + ty * 4 + i;
        if (r < M) {
            int tok = (MODE == 0) ? g_perm[base + r] : r;
            float* o = Out + (size_t)tok * DM + n0 + tx * 4;
            if (MODE == 0) {
                *(float4*)o = make_float4(acc[i][0], acc[i][1], acc[i][2], acc[i][3]);
            } else {
                float4 p = *(const float4*)o;   // unique writer per element in this kernel
                p.x += acc[i][0]; p.y += acc[i][1];
                p.z += acc[i][2]; p.w += acc[i][3];
                *(float4*)o = p;
            }
        }
    }
}

// ---------------- launch ----------------
extern "C" void kernel_launch(void* const* d_in, const int* in_sizes, int n_in,
                              void* d_out, int out_size) {
    const float* hidden   = (const float*)d_in[0];  // [1024,2,2048] -> [T, D] rows
    const float* router_w = (const float*)d_in[1];  // [D, E]
    const float* gate_w   = (const float*)d_in[2];  // [E, D, F]
    const float* up_w     = (const float*)d_in[3];  // [E, D, F]
    const float* down_w   = (const float*)d_in[4];  // [E, F, D]
    const float* sgate    = (const float*)d_in[5];  // [D, F]
    const float* sup      = (const float*)d_in[6];  // [D, F]
    const float* sdown    = (const float*)d_in[7];  // [F, D]
    float* out = (float*)d_out;                     // [T, D]

    init_kernel<<<1, 32>>>();
    router_kernel<<<T, 256>>>(hidden, router_w);
    scan_kernel<<<1, 32>>>();
    scatter_kernel<<<T / 256, 256>>>();

    dim3 gr(FF / 64, T / 64, NE);    // routed tiles (most exit via count check)
    dim3 gs(FF / 64, T / 64, 1);     // shared tiles
    gemm_gateup_kernel<0><<<gr, 256>>>(nullptr, gate_w, up_w);
    gemm_gateup_kernel<1><<<gs, 256>>>(hidden, sgate, sup);

    dim3 dr(DM / 64, T / 64, NE);
    dim3 ds(DM / 64, T / 64, 1);
    gemm_down_kernel<0><<<dr, 256>>>(down_w, out);     // scatter-overwrite: covers all tokens
    gemm_down_kernel<1><<<ds, 256>>>(sdown, out);      // accumulate shared expert
}

// round 4
// speedup vs baseline: 2.8574x; 2.8574x over previous
#include <cuda_runtime.h>
#include <math.h>
#include <stdint.h>

#define T 2048      // tokens
#define DM 2048     // model dim
#define FF 2048     // ffn dim
#define NE 8        // experts
#define BM 128
#define BN 128
#define BK 32
#define NKT (DM/BK)   // 64 k-stages

// smem layout constants (floats)
#define A_STRIDE 36                    // 32 + 4 pad
#define B_STRIDE 136                   // 128 + 8 pad
#define A_BYTES (BM * A_STRIDE * 4)    // 18432
#define B_BYTES (BK * B_STRIDE * 4)    // 17408
#define GU_STAGE (A_BYTES + 2 * B_BYTES)   // 53248
#define GU_SMEM  (2 * GU_STAGE)            // 106496
#define DN_STAGE (A_BYTES + B_BYTES)       // 35840
#define DN_SMEM  (2 * DN_STAGE)            // 71680

// ---------------- scratch (device globals) ----------------
__device__ __align__(16) float g_xs[(size_t)T * DM];
__device__ __align__(16) float g_h [(size_t)T * FF];
__device__ __align__(16) float g_hs[(size_t)T * FF];
__device__ int g_eidx[T];
__device__ int g_counts[NE];
__device__ int g_offsets[NE];
__device__ int g_cursor[NE];
__device__ int g_perm[T];

// ---------------- PTX helpers ----------------
__device__ __forceinline__ void cp16(uint32_t dst, const void* src, bool pred) {
    int bytes = pred ? 16 : 0;
    asm volatile("cp.async.cg.shared.global [%0], [%1], 16, %2;"
                 :: "r"(dst), "l"(src), "r"(bytes) : "memory");
}
#define CP_COMMIT() asm volatile("cp.async.commit_group;" ::: "memory")
#define CP_WAIT1()  asm volatile("cp.async.wait_group 1;" ::: "memory")
#define CP_WAIT0()  asm volatile("cp.async.wait_group 0;" ::: "memory")

__device__ __forceinline__ uint32_t smem_u32(const void* p) {
    uint32_t a;
    asm("{ .reg .u64 t; cvta.to.shared.u64 t, %1; cvt.u32.u64 %0, t; }" : "=r"(a) : "l"(p));
    return a;
}
// round-to-nearest tf32, return bit pattern for mma operand
__device__ __forceinline__ uint32_t tf(float x) {
    float y; asm("cvt.rna.tf32.f32 %0, %1;" : "=f"(y) : "f"(x));
    return __float_as_uint(y);
}
__device__ __forceinline__ void mma8(float* c, const uint32_t* a, uint32_t b0, uint32_t b1) {
    asm volatile("mma.sync.aligned.m16n8k8.row.col.f32.tf32.tf32.f32 "
                 "{%0,%1,%2,%3}, {%4,%5,%6,%7}, {%8,%9}, {%0,%1,%2,%3};"
                 : "+f"(c[0]), "+f"(c[1]), "+f"(c[2]), "+f"(c[3])
                 : "r"(a[0]), "r"(a[1]), "r"(a[2]), "r"(a[3]), "r"(b0), "r"(b1));
}

// ---------------- router / routing bookkeeping ----------------
__global__ void init_kernel() { if (threadIdx.x < NE) g_counts[threadIdx.x] = 0; }

__global__ void __launch_bounds__(256) router_kernel(const float* __restrict__ x,
                                                     const float* __restrict__ rw) {
    int t = blockIdx.x;
    const float* xr = x + (size_t)t * DM;
    float acc[NE];
#pragma unroll
    for (int e = 0; e < NE; e++) acc[e] = 0.f;
    for (int d = threadIdx.x; d < DM; d += 256) {
        float xv = xr[d];
        const float* r = rw + (size_t)d * NE;
#pragma unroll
        for (int e = 0; e < NE; e++) acc[e] = fmaf(xv, r[e], acc[e]);
    }
    __shared__ float sacc[8][NE];
    __shared__ float s_score;
    int lane = threadIdx.x & 31, warp = threadIdx.x >> 5;
#pragma unroll
    for (int e = 0; e < NE; e++) {
        float v = acc[e];
#pragma unroll
        for (int o = 16; o > 0; o >>= 1) v += __shfl_down_sync(0xffffffffu, v, o);
        if (lane == 0) sacc[warp][e] = v;
    }
    __syncthreads();
    if (threadIdx.x == 0) {
        float best = -INFINITY; int bi = 0;
#pragma unroll
        for (int e = 0; e < NE; e++) {
            float v = 0.f;
#pragma unroll
            for (int w = 0; w < 8; w++) v += sacc[w][e];
            if (v > best) { best = v; bi = e; }
        }
        s_score = 1.f / (1.f + expf(-best));
        g_eidx[t] = bi;
        atomicAdd(&g_counts[bi], 1);
    }
    __syncthreads();
    float sc = s_score;
    for (int d = threadIdx.x; d < DM; d += 256)
        g_xs[(size_t)t * DM + d] = xr[d] * sc;
}

__global__ void scan_kernel() {
    if (threadIdx.x == 0) {
        int off = 0;
        for (int e = 0; e < NE; e++) { g_offsets[e] = off; g_cursor[e] = off; off += g_counts[e]; }
    }
}
__global__ void scatter_kernel() {
    int t = blockIdx.x * blockDim.x + threadIdx.x;
    if (t < T) { int e = g_eidx[t]; int pos = atomicAdd(&g_cursor[e], 1); g_perm[pos] = t; }
}

// ================= gate/up GEMM + fused SwiGLU (mma.sync tf32) =================
template<int MODE>
__global__ void __launch_bounds__(256) gateup_mma(const float* __restrict__ Xs,
                                                  const float* __restrict__ Wg_all,
                                                  const float* __restrict__ Wu_all) {
    int e    = (MODE == 0) ? blockIdx.z : 0;
    int Mcnt = (MODE == 0) ? g_counts[e] : T;
    int base = (MODE == 0) ? g_offsets[e] : 0;
    int m0 = blockIdx.y * BM;
    if (m0 >= Mcnt) return;
    int n0 = blockIdx.x * BN;
    const float* A = (MODE == 0) ? g_xs : Xs;
    float* Hout = (MODE == 0) ? g_h : g_hs;
    const float* Wg = Wg_all + (size_t)e * DM * FF;
    const float* Wu = Wu_all + (size_t)e * DM * FF;

    extern __shared__ char smem[];
    uint32_t sb = smem_u32(smem);
    int tid = threadIdx.x, wid = tid >> 5, lane = tid & 31;
    int wm = wid >> 2, wn = wid & 3;          // 2x4 warp grid, warp tile 64x32
    int grp = lane >> 2, tg = lane & 3;

    // ---- load assignments ----
    // A: thread -> (m = tid/8 + 32i, k4 = tid%8), i=0..3
    const float* aptr[4];
    uint32_t aso[4];
    {
        int kg = tid & 7;
#pragma unroll
        for (int i = 0; i < 4; i++) {
            int r = (tid >> 3) + i * 32;
            int gr = m0 + r;
            if (gr < Mcnt) {
                int tok = (MODE == 0) ? g_perm[base + gr] : gr;
                aptr[i] = A + (size_t)tok * DM + kg * 4;
            } else aptr[i] = nullptr;
            aso[i] = (uint32_t)((r * A_STRIDE + kg * 4) * 4);
        }
    }
    // B: thread -> (k = tid/32 + 8i, n4 = tid%32), i=0..3
    const float* bgp; const float* bup;
    uint32_t bso[4];
    {
        int n4 = tid & 31, k = tid >> 5;
        bgp = Wg + (size_t)k * FF + n0 + n4 * 4;
        bup = Wu + (size_t)k * FF + n0 + n4 * 4;
#pragma unroll
        for (int i = 0; i < 4; i++)
            bso[i] = (uint32_t)(((k + i * 8) * B_STRIDE + n4 * 4) * 4);
    }

    float accg[4][4][4], accu[4][4][4];
#pragma unroll
    for (int mt = 0; mt < 4; mt++)
#pragma unroll
        for (int nt = 0; nt < 4; nt++)
#pragma unroll
            for (int c = 0; c < 4; c++) { accg[mt][nt][c] = 0.f; accu[mt][nt][c] = 0.f; }

    // ---- async load of one k-stage into buffer b ----
    auto load_stage = [&](int kt, int b) {
        uint32_t sA = sb + b * GU_STAGE;
        uint32_t sG = sA + A_BYTES;
        uint32_t sU = sG + B_BYTES;
        int k0 = kt * BK;
#pragma unroll
        for (int i = 0; i < 4; i++)
            cp16(sA + aso[i], aptr[i] ? (aptr[i] + k0) : (const float*)A, aptr[i] != nullptr);
        const float* g = bgp + (size_t)k0 * FF;
        const float* u = bup + (size_t)k0 * FF;
#pragma unroll
        for (int i = 0; i < 4; i++) {
            cp16(sG + bso[i], g + (size_t)i * 8 * FF, true);
            cp16(sU + bso[i], u + (size_t)i * 8 * FF, true);
        }
    };

    load_stage(0, 0); CP_COMMIT();
    load_stage(1, 1); CP_COMMIT();

    for (int kt = 0; kt < NKT; kt++) {
        if (kt == NKT - 1) { CP_WAIT0(); } else { CP_WAIT1(); }
        __syncthreads();
        int b = kt & 1;
        const float* As = (const float*)(smem + b * GU_STAGE);
        const float* Bg = (const float*)(smem + b * GU_STAGE + A_BYTES);
        const float* Bu = (const float*)(smem + b * GU_STAGE + A_BYTES + B_BYTES);
#pragma unroll
        for (int k8 = 0; k8 < BK; k8 += 8) {
            uint32_t af[4][4];
#pragma unroll
            for (int mt = 0; mt < 4; mt++) {
                const float* ab = As + (wm * 64 + mt * 16 + grp) * A_STRIDE + k8 + tg;
                af[mt][0] = tf(ab[0]);
                af[mt][1] = tf(ab[8 * A_STRIDE]);
                af[mt][2] = tf(ab[4]);
                af[mt][3] = tf(ab[8 * A_STRIDE + 4]);
            }
#pragma unroll
            for (int nt = 0; nt < 4; nt++) {
                int c = wn * 32 + nt * 8 + grp;
                const float* gb = Bg + (k8 + tg) * B_STRIDE + c;
                const float* ub = Bu + (k8 + tg) * B_STRIDE + c;
                uint32_t g0 = tf(gb[0]), g1 = tf(gb[4 * B_STRIDE]);
                uint32_t u0 = tf(ub[0]), u1 = tf(ub[4 * B_STRIDE]);
#pragma unroll
                for (int mt = 0; mt < 4; mt++) {
                    mma8(accg[mt][nt], af[mt], g0, g1);
                    mma8(accu[mt][nt], af[mt], u0, u1);
                }
            }
        }
        __syncthreads();
        if (kt + 2 < NKT) { load_stage(kt + 2, b); CP_COMMIT(); }
    }

    // ---- epilogue: h = silu(g) * u ----
#pragma unroll
    for (int mt = 0; mt < 4; mt++) {
        int row0 = m0 + wm * 64 + mt * 16 + grp;
#pragma unroll
        for (int half = 0; half < 2; half++) {
            int r = row0 + half * 8;
            if (r < Mcnt) {
                float* orow = Hout + (size_t)(base + r) * FF + n0 + wn * 32;
#pragma unroll
                for (int nt = 0; nt < 4; nt++) {
                    float gx = accg[mt][nt][half * 2 + 0];
                    float gy = accg[mt][nt][half * 2 + 1];
                    float hx = gx / (1.f + expf(-gx)) * accu[mt][nt][half * 2 + 0];
                    float hy = gy / (1.f + expf(-gy)) * accu[mt][nt][half * 2 + 1];
                    *(float2*)(orow + nt * 8 + tg * 2) = make_float2(hx, hy);
                }
            }
        }
    }
}

// ================= down GEMM (mma.sync tf32) =================
template<int MODE>
__global__ void __launch_bounds__(256) down_mma(const float* __restrict__ W_all,
                                                float* __restrict__ Out) {
    int e    = (MODE == 0) ? blockIdx.z : 0;
    int Mcnt = (MODE == 0) ? g_counts[e] : T;
    int base = (MODE == 0) ? g_offsets[e] : 0;
    int m0 = blockIdx.y * BM;
    if (m0 >= Mcnt) return;
    int n0 = blockIdx.x * BN;
    const float* A = (MODE == 0) ? g_h : g_hs;
    const float* W = W_all + (size_t)e * FF * DM;

    extern __shared__ char smem[];
    uint32_t sb = smem_u32(smem);
    int tid = threadIdx.x, wid = tid >> 5, lane = tid & 31;
    int wm = wid >> 2, wn = wid & 3;
    int grp = lane >> 2, tg = lane & 3;

    const float* aptr[4];
    uint32_t aso[4];
    {
        int kg = tid & 7;
#pragma unroll
        for (int i = 0; i < 4; i++) {
            int r = (tid >> 3) + i * 32;
            int gr = m0 + r;
            aptr[i] = (gr < Mcnt) ? (A + (size_t)(base + gr) * FF + kg * 4) : nullptr;
            aso[i] = (uint32_t)((r * A_STRIDE + kg * 4) * 4);
        }
    }
    const float* wp;
    uint32_t bso[4];
    {
        int n4 = tid & 31, k = tid >> 5;
        wp = W + (size_t)k * DM + n0 + n4 * 4;
#pragma unroll
        for (int i = 0; i < 4; i++)
            bso[i] = (uint32_t)(((k + i * 8) * B_STRIDE + n4 * 4) * 4);
    }

    float acc[4][4][4];
#pragma unroll
    for (int mt = 0; mt < 4; mt++)
#pragma unroll
        for (int nt = 0; nt < 4; nt++)
#pragma unroll
            for (int c = 0; c < 4; c++) acc[mt][nt][c] = 0.f;

    auto load_stage = [&](int kt, int b) {
        uint32_t sA = sb + b * DN_STAGE;
        uint32_t sB = sA + A_BYTES;
        int k0 = kt * BK;
#pragma unroll
        for (int i = 0; i < 4; i++)
            cp16(sA + aso[i], aptr[i] ? (aptr[i] + k0) : (const float*)A, aptr[i] != nullptr);
        const float* w = wp + (size_t)k0 * DM;
#pragma unroll
        for (int i = 0; i < 4; i++)
            cp16(sB + bso[i], w + (size_t)i * 8 * DM, true);
    };

    load_stage(0, 0); CP_COMMIT();
    load_stage(1, 1); CP_COMMIT();

    for (int kt = 0; kt < NKT; kt++) {
        if (kt == NKT - 1) { CP_WAIT0(); } else { CP_WAIT1(); }
        __syncthreads();
        int b = kt & 1;
        const float* As = (const float*)(smem + b * DN_STAGE);
        const float* Bs = (const float*)(smem + b * DN_STAGE + A_BYTES);
#pragma unroll
        for (int k8 = 0; k8 < BK; k8 += 8) {
            uint32_t af[4][4];
#pragma unroll
            for (int mt = 0; mt < 4; mt++) {
                const float* ab = As + (wm * 64 + mt * 16 + grp) * A_STRIDE + k8 + tg;
                af[mt][0] = tf(ab[0]);
                af[mt][1] = tf(ab[8 * A_STRIDE]);
                af[mt][2] = tf(ab[4]);
                af[mt][3] = tf(ab[8 * A_STRIDE + 4]);
            }
#pragma unroll
            for (int nt = 0; nt < 4; nt++) {
                int c = wn * 32 + nt * 8 + grp;
                const float* bb = Bs + (k8 + tg) * B_STRIDE + c;
                uint32_t b0 = tf(bb[0]), b1 = tf(bb[4 * B_STRIDE]);
#pragma unroll
                for (int mt = 0; mt < 4; mt++)
                    mma8(acc[mt][nt], af[mt], b0, b1);
            }
        }
        __syncthreads();
        if (kt + 2 < NKT) { load_stage(kt + 2, b); CP_COMMIT(); }
    }

    // ---- epilogue: scatter (MODE 0 overwrite) / accumulate (MODE 1) ----
#pragma unroll
    for (int mt = 0; mt < 4; mt++) {
        int row0 = m0 + wm * 64 + mt * 16 + grp;
#pragma unroll
        for (int half = 0; half < 2; half++) {
            int r = row0 + half * 8;
            if (r < Mcnt) {
                int tok = (MODE == 0) ? g_perm[base + r] : r;
                float* orow = Out + (size_t)tok * DM + n0 + wn * 32;
#pragma unroll
                for (int nt = 0; nt < 4; nt++) {
                    float vx = acc[mt][nt][half * 2 + 0];
                    float vy = acc[mt][nt][half * 2 + 1];
                    float* o = orow + nt * 8 + tg * 2;
                    if (MODE == 0) {
                        *(float2*)o = make_float2(vx, vy);
                    } else {
                        float2 p = *(const float2*)o;
                        *(float2*)o = make_float2(p.x + vx, p.y + vy);
                    }
                }
            }
        }
    }
}

// ---------------- launch ----------------
extern "C" void kernel_launch(void* const* d_in, const int* in_sizes, int n_in,
                              void* d_out, int out_size) {
    const float* hidden   = (const float*)d_in[0];
    const float* router_w = (const float*)d_in[1];
    const float* gate_w   = (const float*)d_in[2];
    const float* up_w     = (const float*)d_in[3];
    const float* down_w   = (const float*)d_in[4];
    const float* sgate    = (const float*)d_in[5];
    const float* sup      = (const float*)d_in[6];
    const float* sdown    = (const float*)d_in[7];
    float* out = (float*)d_out;

    cudaFuncSetAttribute(gateup_mma<0>, cudaFuncAttributeMaxDynamicSharedMemorySize, GU_SMEM);
    cudaFuncSetAttribute(gateup_mma<1>, cudaFuncAttributeMaxDynamicSharedMemorySize, GU_SMEM);
    cudaFuncSetAttribute(down_mma<0>,   cudaFuncAttributeMaxDynamicSharedMemorySize, DN_SMEM);
    cudaFuncSetAttribute(down_mma<1>,   cudaFuncAttributeMaxDynamicSharedMemorySize, DN_SMEM);

    init_kernel<<<1, 32>>>();
    router_kernel<<<T, 256>>>(hidden, router_w);
    scan_kernel<<<1, 32>>>();
    scatter_kernel<<<T / 256, 256>>>();

    dim3 gr(FF / BN, T / BM, NE);   // routed (most tiles early-exit)
    dim3 gs(FF / BN, T / BM, 1);    // shared
    gateup_mma<0><<<gr, 256, GU_SMEM>>>(nullptr, gate_w, up_w);
    gateup_mma<1><<<gs, 256, GU_SMEM>>>(hidden, sgate, sup);

    dim3 dr(DM / BN, T / BM, NE);
    dim3 ds(DM / BN, T / BM, 1);
    down_mma<0><<<dr, 256, DN_SMEM>>>(down_w, out);    // scatter-overwrite (covers all tokens)
    down_mma<1><<<ds, 256, DN_SMEM>>>(sdown, out);     // accumulate shared expert
}

// round 6
// speedup vs baseline: 2.9510x; 1.0327x over previous
#include <cuda_runtime.h>
#include <math.h>
#include <stdint.h>

#define T 2048      // tokens
#define DM 2048     // model dim
#define FF 2048     // ffn dim
#define NE 8        // experts
#define BM 128
#define BN 128
#define BK 32
#define NKT (DM/BK)   // 64 k-stages

// smem layout constants (floats)
#define A_STRIDE 36                    // 32 + 4 pad
#define B_STRIDE 136                   // 128 + 8 pad
#define A_BYTES (BM * A_STRIDE * 4)    // 18432
#define B_BYTES (BK * B_STRIDE * 4)    // 17408
#define GU_STAGE (A_BYTES + 2 * B_BYTES)   // 53248
#define GU_SMEM  (2 * GU_STAGE)            // 106496
#define DN_STAGE (A_BYTES + B_BYTES)       // 35840
#define DN_SMEM  (2 * DN_STAGE)            // 71680

// ---------------- scratch (device globals) ----------------
__device__ __align__(16) float g_xs[(size_t)T * DM];   // rna(x * score)
__device__ __align__(16) float g_xr[(size_t)T * DM];   // rna(x)   (shared-expert A)
__device__ __align__(16) float g_h [(size_t)T * FF];   // rna(routed swiglu)
__device__ __align__(16) float g_hs[(size_t)T * FF];   // rna(shared swiglu)
__device__ int g_eidx[T];
__device__ int g_counts[NE];
__device__ int g_offsets[NE];
__device__ int g_cursor[NE];
__device__ int g_perm[T];

// ---------------- PTX helpers ----------------
__device__ __forceinline__ void cp16(uint32_t dst, const void* src, bool pred) {
    int bytes = pred ? 16 : 0;
    asm volatile("cp.async.cg.shared.global [%0], [%1], 16, %2;"
                 :: "r"(dst), "l"(src), "r"(bytes) : "memory");
}
#define CP_COMMIT() asm volatile("cp.async.commit_group;" ::: "memory")
#define CP_WAIT1()  asm volatile("cp.async.wait_group 1;" ::: "memory")
#define CP_WAIT0()  asm volatile("cp.async.wait_group 0;" ::: "memory")

__device__ __forceinline__ uint32_t smem_u32(const void* p) {
    uint32_t a;
    asm("{ .reg .u64 t; cvta.to.shared.u64 t, %1; cvt.u32.u64 %0, t; }" : "=r"(a) : "l"(p));
    return a;
}
// round-to-nearest tf32
__device__ __forceinline__ uint32_t tf(float x) {
    float y; asm("cvt.rna.tf32.f32 %0, %1;" : "=f"(y) : "f"(x));
    return __float_as_uint(y);
}
__device__ __forceinline__ float rnaf(float x) {
    float y; asm("cvt.rna.tf32.f32 %0, %1;" : "=f"(y) : "f"(x));
    return y;
}
__device__ __forceinline__ void mma8(float* c, const uint32_t* a, uint32_t b0, uint32_t b1) {
    asm volatile("mma.sync.aligned.m16n8k8.row.col.f32.tf32.tf32.f32 "
                 "{%0,%1,%2,%3}, {%4,%5,%6,%7}, {%8,%9}, {%0,%1,%2,%3};"
                 : "+f"(c[0]), "+f"(c[1]), "+f"(c[2]), "+f"(c[3])
                 : "r"(a[0]), "r"(a[1]), "r"(a[2]), "r"(a[3]), "r"(b0), "r"(b1));
}

// ---------------- router / routing bookkeeping ----------------
__global__ void init_kernel() { if (threadIdx.x < NE) g_counts[threadIdx.x] = 0; }

__global__ void __launch_bounds__(256) router_kernel(const float* __restrict__ x,
                                                     const float* __restrict__ rw) {
    int t = blockIdx.x;
    const float* xr = x + (size_t)t * DM;
    float acc[NE];
#pragma unroll
    for (int e = 0; e < NE; e++) acc[e] = 0.f;
    for (int d = threadIdx.x; d < DM; d += 256) {
        float xv = xr[d];
        const float* r = rw + (size_t)d * NE;
#pragma unroll
        for (int e = 0; e < NE; e++) acc[e] = fmaf(xv, r[e], acc[e]);
    }
    __shared__ float sacc[8][NE];
    __shared__ float s_score;
    int lane = threadIdx.x & 31, warp = threadIdx.x >> 5;
#pragma unroll
    for (int e = 0; e < NE; e++) {
        float v = acc[e];
#pragma unroll
        for (int o = 16; o > 0; o >>= 1) v += __shfl_down_sync(0xffffffffu, v, o);
        if (lane == 0) sacc[warp][e] = v;
    }
    __syncthreads();
    if (threadIdx.x == 0) {
        float best = -INFINITY; int bi = 0;
#pragma unroll
        for (int e = 0; e < NE; e++) {
            float v = 0.f;
#pragma unroll
            for (int w = 0; w < 8; w++) v += sacc[w][e];
            if (v > best) { best = v; bi = e; }
        }
        s_score = 1.f / (1.f + expf(-best));
        g_eidx[t] = bi;
        atomicAdd(&g_counts[bi], 1);
    }
    __syncthreads();
    float sc = s_score;
    for (int d = threadIdx.x; d < DM; d += 256) {
        float xv = xr[d];
        g_xs[(size_t)t * DM + d] = rnaf(xv * sc);
        g_xr[(size_t)t * DM + d] = rnaf(xv);
    }
}

__global__ void scan_kernel() {
    if (threadIdx.x == 0) {
        int off = 0;
        for (int e = 0; e < NE; e++) { g_offsets[e] = off; g_cursor[e] = off; off += g_counts[e]; }
    }
}
__global__ void scatter_kernel() {
    int t = blockIdx.x * blockDim.x + threadIdx.x;
    if (t < T) { int e = g_eidx[t]; int pos = atomicAdd(&g_cursor[e], 1); g_perm[pos] = t; }
}

// ================= gate/up GEMM + fused SwiGLU (merged routed z<8 / shared z==8) =================
__global__ void __launch_bounds__(512) gateup_mma(const float* __restrict__ Wg_all,
                                                  const float* __restrict__ Wu_all,
                                                  const float* __restrict__ Wsg,
                                                  const float* __restrict__ Wsu) {
    int e = blockIdx.z;
    bool sh = (e == NE);
    int Mcnt = sh ? T : g_counts[e];
    int base = sh ? 0 : g_offsets[e];
    int m0 = blockIdx.y * BM;
    if (m0 >= Mcnt) return;
    int n0 = blockIdx.x * BN;
    const float* A = sh ? g_xr : g_xs;
    float* Hout = sh ? g_hs : g_h;
    const float* Wg = sh ? Wsg : Wg_all + (size_t)e * DM * FF;
    const float* Wu = sh ? Wsu : Wu_all + (size_t)e * DM * FF;

    extern __shared__ char smem[];
    uint32_t sb = smem_u32(smem);
    int tid = threadIdx.x, wid = tid >> 5, lane = tid & 31;
    int wm = wid & 3, wn = wid >> 2;          // 4x4 warp grid, warp tile 32x32
    int grp = lane >> 2, tg = lane & 3;

    // ---- load assignments ----
    // A: thread -> one row (tid/4), two float4 slots (q0, q0+4)
    const float* arow = nullptr;
    uint32_t aso[2];
    {
        int r = tid >> 2, q0 = tid & 3;
        int gr = m0 + r;
        if (gr < Mcnt) {
            int tok = sh ? gr : g_perm[base + gr];
            arow = A + (size_t)tok * DM;
        }
        aso[0] = (uint32_t)((r * A_STRIDE + q0 * 4) * 4);
        aso[1] = (uint32_t)((r * A_STRIDE + (q0 + 4) * 4) * 4);
    }
    int q0 = tid & 3;
    // B: thread -> (k = tid/32 + 16i, n4 = tid%32)
    const float* bgp; const float* bup;
    uint32_t bso[2];
    {
        int n4 = tid & 31, kb = tid >> 5;  // kb 0..15
        bgp = Wg + (size_t)kb * FF + n0 + n4 * 4;
        bup = Wu + (size_t)kb * FF + n0 + n4 * 4;
#pragma unroll
        for (int i = 0; i < 2; i++)
            bso[i] = (uint32_t)(((kb + i * 16) * B_STRIDE + n4 * 4) * 4);
    }

    float accg[2][4][4], accu[2][4][4];
#pragma unroll
    for (int mt = 0; mt < 2; mt++)
#pragma unroll
        for (int nt = 0; nt < 4; nt++)
#pragma unroll
            for (int c = 0; c < 4; c++) { accg[mt][nt][c] = 0.f; accu[mt][nt][c] = 0.f; }

    auto load_stage = [&](int kt, int b) {
        uint32_t sA = sb + b * GU_STAGE;
        uint32_t sG = sA + A_BYTES;
        uint32_t sU = sG + B_BYTES;
        int k0 = kt * BK;
        cp16(sA + aso[0], arow ? (arow + k0 + q0 * 4) : (const float*)g_xs, arow != nullptr);
        cp16(sA + aso[1], arow ? (arow + k0 + (q0 + 4) * 4) : (const float*)g_xs, arow != nullptr);
#pragma unroll
        for (int i = 0; i < 2; i++) {
            cp16(sG + bso[i], bgp + (size_t)(k0 + i * 16) * FF, true);
            cp16(sU + bso[i], bup + (size_t)(k0 + i * 16) * FF, true);
        }
    };

    load_stage(0, 0); CP_COMMIT();
    load_stage(1, 1); CP_COMMIT();

    for (int kt = 0; kt < NKT; kt++) {
        if (kt == NKT - 1) { CP_WAIT0(); } else { CP_WAIT1(); }
        __syncthreads();
        int b = kt & 1;
        const float* As = (const float*)(smem + b * GU_STAGE);
        const float* Bg = (const float*)(smem + b * GU_STAGE + A_BYTES);
        const float* Bu = (const float*)(smem + b * GU_STAGE + A_BYTES + B_BYTES);
#pragma unroll
        for (int k8 = 0; k8 < BK; k8 += 8) {
            uint32_t af[2][4];
#pragma unroll
            for (int mt = 0; mt < 2; mt++) {
                const uint32_t* ab = (const uint32_t*)(As + (wm * 32 + mt * 16 + grp) * A_STRIDE + k8 + tg);
                af[mt][0] = ab[0];
                af[mt][1] = ab[8 * A_STRIDE];
                af[mt][2] = ab[4];
                af[mt][3] = ab[8 * A_STRIDE + 4];
            }
#pragma unroll
            for (int nt = 0; nt < 4; nt++) {
                int c = wn * 32 + nt * 8 + grp;
                const float* gb = Bg + (k8 + tg) * B_STRIDE + c;
                const float* ub = Bu + (k8 + tg) * B_STRIDE + c;
                uint32_t g0 = tf(gb[0]), g1 = tf(gb[4 * B_STRIDE]);
                uint32_t u0 = tf(ub[0]), u1 = tf(ub[4 * B_STRIDE]);
#pragma unroll
                for (int mt = 0; mt < 2; mt++) {
                    mma8(accg[mt][nt], af[mt], g0, g1);
                    mma8(accu[mt][nt], af[mt], u0, u1);
                }
            }
        }
        __syncthreads();
        if (kt + 2 < NKT) { load_stage(kt + 2, b); CP_COMMIT(); }
    }

    // ---- epilogue: h = rna(silu(g) * u) (pre-rounded for the down GEMM) ----
#pragma unroll
    for (int mt = 0; mt < 2; mt++) {
        int row0 = m0 + wm * 32 + mt * 16 + grp;
#pragma unroll
        for (int half = 0; half < 2; half++) {
            int r = row0 + half * 8;
            if (r < Mcnt) {
                float* orow = Hout + (size_t)(base + r) * FF + n0 + wn * 32;
#pragma unroll
                for (int nt = 0; nt < 4; nt++) {
                    float gx = accg[mt][nt][half * 2 + 0];
                    float gy = accg[mt][nt][half * 2 + 1];
                    float hx = rnaf(gx / (1.f + expf(-gx)) * accu[mt][nt][half * 2 + 0]);
                    float hy = rnaf(gy / (1.f + expf(-gy)) * accu[mt][nt][half * 2 + 1]);
                    *(float2*)(orow + nt * 8 + tg * 2) = make_float2(hx, hy);
                }
            }
        }
    }
}

// ================= down GEMM (mma.sync tf32) =================
template<int MODE>   // 0: routed scatter-overwrite, 1: shared accumulate
__global__ void __launch_bounds__(512) down_mma(const float* __restrict__ W_all,
                                                float* __restrict__ Out) {
    int e    = (MODE == 0) ? blockIdx.z : 0;
    int Mcnt = (MODE == 0) ? g_counts[e] : T;
    int base = (MODE == 0) ? g_offsets[e] : 0;
    int m0 = blockIdx.y * BM;
    if (m0 >= Mcnt) return;
    int n0 = blockIdx.x * BN;
    const float* A = (MODE == 0) ? g_h : g_hs;
    const float* W = W_all + (size_t)e * FF * DM;

    extern __shared__ char smem[];
    uint32_t sb = smem_u32(smem);
    int tid = threadIdx.x, wid = tid >> 5, lane = tid & 31;
    int wm = wid & 3, wn = wid >> 2;
    int grp = lane >> 2, tg = lane & 3;

    const float* arow = nullptr;
    uint32_t aso[2];
    {
        int r = tid >> 2;
        int gr = m0 + r;
        if (gr < Mcnt) arow = A + (size_t)(base + gr) * FF;
        int qq = tid & 3;
        aso[0] = (uint32_t)((r * A_STRIDE + qq * 4) * 4);
        aso[1] = (uint32_t)((r * A_STRIDE + (qq + 4) * 4) * 4);
    }
    int q0 = tid & 3;
    const float* wp;
    uint32_t bso[2];
    {
        int n4 = tid & 31, kb = tid >> 5;
        wp = W + (size_t)kb * DM + n0 + n4 * 4;
#pragma unroll
        for (int i = 0; i < 2; i++)
            bso[i] = (uint32_t)(((kb + i * 16) * B_STRIDE + n4 * 4) * 4);
    }

    float acc[2][4][4];
#pragma unroll
    for (int mt = 0; mt < 2; mt++)
#pragma unroll
        for (int nt = 0; nt < 4; nt++)
#pragma unroll
            for (int c = 0; c < 4; c++) acc[mt][nt][c] = 0.f;

    auto load_stage = [&](int kt, int b) {
        uint32_t sA = sb + b * DN_STAGE;
        uint32_t sB = sA + A_BYTES;
        int k0 = kt * BK;
        cp16(sA + aso[0], arow ? (arow + k0 + q0 * 4) : (const float*)g_h, arow != nullptr);
        cp16(sA + aso[1], arow ? (arow + k0 + (q0 + 4) * 4) : (const float*)g_h, arow != nullptr);
#pragma unroll
        for (int i = 0; i < 2; i++)
            cp16(sB + bso[i], wp + (size_t)(k0 + i * 16) * DM, true);
    };

    load_stage(0, 0); CP_COMMIT();
    load_stage(1, 1); CP_COMMIT();

    for (int kt = 0; kt < NKT; kt++) {
        if (kt == NKT - 1) { CP_WAIT0(); } else { CP_WAIT1(); }
        __syncthreads();
        int b = kt & 1;
        const float* As = (const float*)(smem + b * DN_STAGE);
        const float* Bs = (const float*)(smem + b * DN_STAGE + A_BYTES);
#pragma unroll
        for (int k8 = 0; k8 < BK; k8 += 8) {
            uint32_t af[2][4];
#pragma unroll
            for (int mt = 0; mt < 2; mt++) {
                const uint32_t* ab = (const uint32_t*)(As + (wm * 32 + mt * 16 + grp) * A_STRIDE + k8 + tg);
                af[mt][0] = ab[0];
                af[mt][1] = ab[8 * A_STRIDE];
                af[mt][2] = ab[4];
                af[mt][3] = ab[8 * A_STRIDE + 4];
            }
#pragma unroll
            for (int nt = 0; nt < 4; nt++) {
                int c = wn * 32 + nt * 8 + grp;
                const float* bb = Bs + (k8 + tg) * B_STRIDE + c;
                uint32_t b0 = tf(bb[0]), b1 = tf(bb[4 * B_STRIDE]);
#pragma unroll
                for (int mt = 0; mt < 2; mt++)
                    mma8(acc[mt][nt], af[mt], b0, b1);
            }
        }
        __syncthreads();
        if (kt + 2 < NKT) { load_stage(kt + 2, b); CP_COMMIT(); }
    }

    // ---- epilogue ----
#pragma unroll
    for (int mt = 0; mt < 2; mt++) {
        int row0 = m0 + wm * 32 + mt * 16 + grp;
#pragma unroll
        for (int half = 0; half < 2; half++) {
            int r = row0 + half * 8;
            if (r < Mcnt) {
                int tok = (MODE == 0) ? g_perm[base + r] : r;
                float* orow = Out + (size_t)tok * DM + n0 + wn * 32;
#pragma unroll
                for (int nt = 0; nt < 4; nt++) {
                    float vx = acc[mt][nt][half * 2 + 0];
                    float vy = acc[mt][nt][half * 2 + 1];
                    float* o = orow + nt * 8 + tg * 2;
                    if (MODE == 0) {
                        *(float2*)o = make_float2(vx, vy);
                    } else {
                        float2 p = *(const float2*)o;
                        *(float2*)o = make_float2(p.x + vx, p.y + vy);
                    }
                }
            }
        }
    }
}

// ---------------- launch ----------------
extern "C" void kernel_launch(void* const* d_in, const int* in_sizes, int n_in,
                              void* d_out, int out_size) {
    const float* hidden   = (const float*)d_in[0];
    const float* router_w = (const float*)d_in[1];
    const float* gate_w   = (const float*)d_in[2];
    const float* up_w     = (const float*)d_in[3];
    const float* down_w   = (const float*)d_in[4];
    const float* sgate    = (const float*)d_in[5];
    const float* sup      = (const float*)d_in[6];
    const float* sdown    = (const float*)d_in[7];
    float* out = (float*)d_out;

    cudaFuncSetAttribute(gateup_mma,  cudaFuncAttributeMaxDynamicSharedMemorySize, GU_SMEM);
    cudaFuncSetAttribute(down_mma<0>, cudaFuncAttributeMaxDynamicSharedMemorySize, DN_SMEM);
    cudaFuncSetAttribute(down_mma<1>, cudaFuncAttributeMaxDynamicSharedMemorySize, DN_SMEM);

    init_kernel<<<1, 32>>>();
    router_kernel<<<T, 256>>>(hidden, router_w);
    scan_kernel<<<1, 32>>>();
    scatter_kernel<<<T / 256, 256>>>();

    dim3 gg(FF / BN, T / BM, NE + 1);   // z: 0..7 routed experts, 8 = shared expert
    gateup_mma<<<gg, 512, GU_SMEM>>>(gate_w, up_w, sgate, sup);

    dim3 dr(DM / BN, T / BM, NE);
    dim3 ds(DM / BN, T / BM, 1);
    down_mma<0><<<dr, 512, DN_SMEM>>>(down_w, out);    // scatter-overwrite (covers all tokens)
    down_mma<1><<<ds, 512, DN_SMEM>>>(sdown, out);     // accumulate shared expert
}

// round 7
// speedup vs baseline: 3.0671x; 1.0394x over previous
#include <cuda_runtime.h>
#include <math.h>
#include <stdint.h>

#define T 2048      // tokens
#define DM 2048     // model dim
#define FF 2048     // ffn dim
#define NE 8        // experts
#define BM 128
#define BN 128
#define BK 32
#define NKT (DM/BK)   // 64 k-stages

// smem layout constants (floats)
#define A_STRIDE 36                    // 32 + 4 pad
#define B_STRIDE 136                   // 128 + 8 pad
#define A_BYTES (BM * A_STRIDE * 4)    // 18432
#define B_BYTES (BK * B_STRIDE * 4)    // 17408
#define GU_STAGE (A_BYTES + 2 * B_BYTES)   // 53248
#define GU_SMEM  (2 * GU_STAGE)            // 106496
#define DN_STAGE (A_BYTES + B_BYTES)       // 35840
#define DN_SMEM  (2 * DN_STAGE)            // 71680

// ---------------- scratch (device globals) ----------------
__device__ __align__(16) float g_xs[(size_t)T * DM];   // rna(x * score)
__device__ __align__(16) float g_xr[(size_t)T * DM];   // rna(x)   (shared-expert A)
__device__ __align__(16) float g_h [(size_t)T * FF];   // rna(routed swiglu)
__device__ __align__(16) float g_hs[(size_t)T * FF];   // rna(shared swiglu)
__device__ int g_eidx[T];
__device__ int g_counts[NE];
__device__ int g_offsets[NE];
__device__ int g_cursor[NE];
__device__ int g_perm[T];

// ---------------- PTX helpers ----------------
__device__ __forceinline__ void cp16(uint32_t dst, const void* src, bool pred) {
    int bytes = pred ? 16 : 0;
    asm volatile("cp.async.cg.shared.global [%0], [%1], 16, %2;"
                 :: "r"(dst), "l"(src), "r"(bytes) : "memory");
}
#define CP_COMMIT() asm volatile("cp.async.commit_group;" ::: "memory")
#define CP_WAIT1()  asm volatile("cp.async.wait_group 1;" ::: "memory")
#define CP_WAIT0()  asm volatile("cp.async.wait_group 0;" ::: "memory")

__device__ __forceinline__ uint32_t smem_u32(const void* p) {
    uint32_t a;
    asm("{ .reg .u64 t; cvta.to.shared.u64 t, %1; cvt.u32.u64 %0, t; }" : "=r"(a) : "l"(p));
    return a;
}
// round-to-nearest tf32
__device__ __forceinline__ uint32_t tf(float x) {
    float y; asm("cvt.rna.tf32.f32 %0, %1;" : "=f"(y) : "f"(x));
    return __float_as_uint(y);
}
__device__ __forceinline__ float rnaf(float x) {
    float y; asm("cvt.rna.tf32.f32 %0, %1;" : "=f"(y) : "f"(x));
    return y;
}
__device__ __forceinline__ void mma8(float* c, const uint32_t* a, uint32_t b0, uint32_t b1) {
    asm volatile("mma.sync.aligned.m16n8k8.row.col.f32.tf32.tf32.f32 "
                 "{%0,%1,%2,%3}, {%4,%5,%6,%7}, {%8,%9}, {%0,%1,%2,%3};"
                 : "+f"(c[0]), "+f"(c[1]), "+f"(c[2]), "+f"(c[3])
                 : "r"(a[0]), "r"(a[1]), "r"(a[2]), "r"(a[3]), "r"(b0), "r"(b1));
}
// ldmatrix x4: loads one full m16k8 tf32 A fragment (matrices 0..3 -> a0..a3)
__device__ __forceinline__ void ldsm4(uint32_t* r, uint32_t addr) {
    asm volatile("ldmatrix.sync.aligned.m8n8.x4.shared.b16 {%0,%1,%2,%3}, [%4];"
                 : "=r"(r[0]), "=r"(r[1]), "=r"(r[2]), "=r"(r[3]) : "r"(addr));
}

// ---------------- router / routing bookkeeping ----------------
__global__ void init_kernel() { if (threadIdx.x < NE) g_counts[threadIdx.x] = 0; }

__global__ void __launch_bounds__(256) router_kernel(const float* __restrict__ x,
                                                     const float* __restrict__ rw) {
    int t = blockIdx.x;
    const float* xr = x + (size_t)t * DM;
    float acc[NE];
#pragma unroll
    for (int e = 0; e < NE; e++) acc[e] = 0.f;
    for (int d = threadIdx.x; d < DM; d += 256) {
        float xv = xr[d];
        const float* r = rw + (size_t)d * NE;
#pragma unroll
        for (int e = 0; e < NE; e++) acc[e] = fmaf(xv, r[e], acc[e]);
    }
    __shared__ float sacc[8][NE];
    __shared__ float s_score;
    int lane = threadIdx.x & 31, warp = threadIdx.x >> 5;
#pragma unroll
    for (int e = 0; e < NE; e++) {
        float v = acc[e];
#pragma unroll
        for (int o = 16; o > 0; o >>= 1) v += __shfl_down_sync(0xffffffffu, v, o);
        if (lane == 0) sacc[warp][e] = v;
    }
    __syncthreads();
    if (threadIdx.x == 0) {
        float best = -INFINITY; int bi = 0;
#pragma unroll
        for (int e = 0; e < NE; e++) {
            float v = 0.f;
#pragma unroll
            for (int w = 0; w < 8; w++) v += sacc[w][e];
            if (v > best) { best = v; bi = e; }
        }
        s_score = 1.f / (1.f + expf(-best));
        g_eidx[t] = bi;
        atomicAdd(&g_counts[bi], 1);
    }
    __syncthreads();
    float sc = s_score;
    for (int d = threadIdx.x; d < DM; d += 256) {
        float xv = xr[d];
        g_xs[(size_t)t * DM + d] = rnaf(xv * sc);
        g_xr[(size_t)t * DM + d] = rnaf(xv);
    }
}

__global__ void scan_kernel() {
    if (threadIdx.x == 0) {
        int off = 0;
        for (int e = 0; e < NE; e++) { g_offsets[e] = off; g_cursor[e] = off; off += g_counts[e]; }
    }
}
__global__ void scatter_kernel() {
    int t = blockIdx.x * blockDim.x + threadIdx.x;
    if (t < T) { int e = g_eidx[t]; int pos = atomicAdd(&g_cursor[e], 1); g_perm[pos] = t; }
}

// ================= gate/up GEMM + fused SwiGLU (merged routed z<8 / shared z==8) =================
// 256 threads, 8 warps in 2x4 grid, warp tile 64x32 (mt=4, nt=4)
__global__ void __launch_bounds__(256) gateup_mma(const float* __restrict__ Wg_all,
                                                  const float* __restrict__ Wu_all,
                                                  const float* __restrict__ Wsg,
                                                  const float* __restrict__ Wsu) {
    int e = blockIdx.z;
    bool sh = (e == NE);
    int Mcnt = sh ? T : g_counts[e];
    int base = sh ? 0 : g_offsets[e];
    int m0 = blockIdx.y * BM;
    if (m0 >= Mcnt) return;
    int n0 = blockIdx.x * BN;
    const float* A = sh ? g_xr : g_xs;
    float* Hout = sh ? g_hs : g_h;
    const float* Wg = sh ? Wsg : Wg_all + (size_t)e * DM * FF;
    const float* Wu = sh ? Wsu : Wu_all + (size_t)e * DM * FF;

    extern __shared__ char smem[];
    uint32_t sb = smem_u32(smem);
    int tid = threadIdx.x, wid = tid >> 5, lane = tid & 31;
    int wm = wid >> 2, wn = wid & 3;          // 2x4 warp grid, warp tile 64x32
    int grp = lane >> 2, tg = lane & 3;

    // ldmatrix per-lane A address offset (bytes) within the tile
    uint32_t a_lm = (uint32_t)((((lane & 7) + ((lane >> 3) & 1) * 8 + wm * 64) * A_STRIDE
                               + (lane >> 4) * 4) * 4);

    // ---- load assignments ----
    // A: thread -> row tid/2, 4 float4 slots starting at (tid&1)*4
    const float* arow = nullptr;
    uint32_t asoA;
    int q0 = (tid & 1) * 4;
    {
        int r = tid >> 1;
        int gr = m0 + r;
        if (gr < Mcnt) {
            int tok = sh ? gr : g_perm[base + gr];
            arow = A + (size_t)tok * DM;
        }
        asoA = (uint32_t)((r * A_STRIDE + q0 * 4) * 4);
    }
    // B: thread -> (k = tid/32 + 8i, n4 = tid%32), i=0..3
    const float* bgp; const float* bup;
    uint32_t bso[4];
    {
        int n4 = tid & 31, kb = tid >> 5;  // kb 0..7
        bgp = Wg + (size_t)kb * FF + n0 + n4 * 4;
        bup = Wu + (size_t)kb * FF + n0 + n4 * 4;
#pragma unroll
        for (int i = 0; i < 4; i++)
            bso[i] = (uint32_t)(((kb + i * 8) * B_STRIDE + n4 * 4) * 4);
    }

    float accg[4][4][4], accu[4][4][4];
#pragma unroll
    for (int mt = 0; mt < 4; mt++)
#pragma unroll
        for (int nt = 0; nt < 4; nt++)
#pragma unroll
            for (int c = 0; c < 4; c++) { accg[mt][nt][c] = 0.f; accu[mt][nt][c] = 0.f; }

    auto load_stage = [&](int kt, int b) {
        uint32_t sA = sb + b * GU_STAGE;
        uint32_t sG = sA + A_BYTES;
        uint32_t sU = sG + B_BYTES;
        int k0 = kt * BK;
#pragma unroll
        for (int j = 0; j < 4; j++)
            cp16(sA + asoA + j * 16, arow ? (arow + k0 + (q0 + j) * 4) : (const float*)g_xs,
                 arow != nullptr);
#pragma unroll
        for (int i = 0; i < 4; i++) {
            cp16(sG + bso[i], bgp + (size_t)(k0 + i * 8) * FF, true);
            cp16(sU + bso[i], bup + (size_t)(k0 + i * 8) * FF, true);
        }
    };

    load_stage(0, 0); CP_COMMIT();
    load_stage(1, 1); CP_COMMIT();

    for (int kt = 0; kt < NKT; kt++) {
        if (kt == NKT - 1) { CP_WAIT0(); } else { CP_WAIT1(); }
        __syncthreads();
        int b = kt & 1;
        uint32_t sA = sb + b * GU_STAGE;
        const float* Bg = (const float*)(smem + b * GU_STAGE + A_BYTES);
        const float* Bu = (const float*)(smem + b * GU_STAGE + A_BYTES + B_BYTES);
        uint32_t abase = sA + a_lm;
#pragma unroll
        for (int k8 = 0; k8 < BK; k8 += 8) {
            uint32_t af[4][4];
#pragma unroll
            for (int mt = 0; mt < 4; mt++)
                ldsm4(af[mt], abase + (uint32_t)(mt * 16 * A_STRIDE * 4 + k8 * 4));
#pragma unroll
            for (int nt = 0; nt < 4; nt++) {
                int c = wn * 32 + nt * 8 + grp;
                const float* gb = Bg + (k8 + tg) * B_STRIDE + c;
                const float* ub = Bu + (k8 + tg) * B_STRIDE + c;
                uint32_t g0 = tf(gb[0]), g1 = tf(gb[4 * B_STRIDE]);
                uint32_t u0 = tf(ub[0]), u1 = tf(ub[4 * B_STRIDE]);
#pragma unroll
                for (int mt = 0; mt < 4; mt++) {
                    mma8(accg[mt][nt], af[mt], g0, g1);
                    mma8(accu[mt][nt], af[mt], u0, u1);
                }
            }
        }
        __syncthreads();
        if (kt + 2 < NKT) { load_stage(kt + 2, b); CP_COMMIT(); }
    }

    // ---- epilogue: h = rna(silu(g) * u) (pre-rounded for the down GEMM) ----
#pragma unroll
    for (int mt = 0; mt < 4; mt++) {
        int row0 = m0 + wm * 64 + mt * 16 + grp;
#pragma unroll
        for (int half = 0; half < 2; half++) {
            int r = row0 + half * 8;
            if (r < Mcnt) {
                float* orow = Hout + (size_t)(base + r) * FF + n0 + wn * 32;
#pragma unroll
                for (int nt = 0; nt < 4; nt++) {
                    float gx = accg[mt][nt][half * 2 + 0];
                    float gy = accg[mt][nt][half * 2 + 1];
                    float hx = rnaf(gx / (1.f + expf(-gx)) * accu[mt][nt][half * 2 + 0]);
                    float hy = rnaf(gy / (1.f + expf(-gy)) * accu[mt][nt][half * 2 + 1]);
                    *(float2*)(orow + nt * 8 + tg * 2) = make_float2(hx, hy);
                }
            }
        }
    }
}

// ================= down GEMM (mma.sync tf32) =================
template<int MODE>   // 0: routed scatter-overwrite, 1: shared accumulate
__global__ void __launch_bounds__(256, 2) down_mma(const float* __restrict__ W_all,
                                                   float* __restrict__ Out) {
    int e    = (MODE == 0) ? blockIdx.z : 0;
    int Mcnt = (MODE == 0) ? g_counts[e] : T;
    int base = (MODE == 0) ? g_offsets[e] : 0;
    int m0 = blockIdx.y * BM;
    if (m0 >= Mcnt) return;
    int n0 = blockIdx.x * BN;
    const float* A = (MODE == 0) ? g_h : g_hs;
    const float* W = W_all + (size_t)e * FF * DM;

    extern __shared__ char smem[];
    uint32_t sb = smem_u32(smem);
    int tid = threadIdx.x, wid = tid >> 5, lane = tid & 31;
    int wm = wid >> 2, wn = wid & 3;
    int grp = lane >> 2, tg = lane & 3;

    uint32_t a_lm = (uint32_t)((((lane & 7) + ((lane >> 3) & 1) * 8 + wm * 64) * A_STRIDE
                               + (lane >> 4) * 4) * 4);

    const float* arow = nullptr;
    uint32_t asoA;
    int q0 = (tid & 1) * 4;
    {
        int r = tid >> 1;
        int gr = m0 + r;
        if (gr < Mcnt) arow = A + (size_t)(base + gr) * FF;
        asoA = (uint32_t)((r * A_STRIDE + q0 * 4) * 4);
    }
    const float* wp;
    uint32_t bso[4];
    {
        int n4 = tid & 31, kb = tid >> 5;
        wp = W + (size_t)kb * DM + n0 + n4 * 4;
#pragma unroll
        for (int i = 0; i < 4; i++)
            bso[i] = (uint32_t)(((kb + i * 8) * B_STRIDE + n4 * 4) * 4);
    }

    float acc[4][4][4];
#pragma unroll
    for (int mt = 0; mt < 4; mt++)
#pragma unroll
        for (int nt = 0; nt < 4; nt++)
#pragma unroll
            for (int c = 0; c < 4; c++) acc[mt][nt][c] = 0.f;

    auto load_stage = [&](int kt, int b) {
        uint32_t sA = sb + b * DN_STAGE;
        uint32_t sB = sA + A_BYTES;
        int k0 = kt * BK;
#pragma unroll
        for (int j = 0; j < 4; j++)
            cp16(sA + asoA + j * 16, arow ? (arow + k0 + (q0 + j) * 4) : (const float*)g_h,
                 arow != nullptr);
#pragma unroll
        for (int i = 0; i < 4; i++)
            cp16(sB + bso[i], wp + (size_t)(k0 + i * 8) * DM, true);
    };

    load_stage(0, 0); CP_COMMIT();
    load_stage(1, 1); CP_COMMIT();

    for (int kt = 0; kt < NKT; kt++) {
        if (kt == NKT - 1) { CP_WAIT0(); } else { CP_WAIT1(); }
        __syncthreads();
        int b = kt & 1;
        uint32_t sA = sb + b * DN_STAGE;
        const float* Bs = (const float*)(smem + b * DN_STAGE + A_BYTES);
        uint32_t abase = sA + a_lm;
#pragma unroll
        for (int k8 = 0; k8 < BK; k8 += 8) {
            uint32_t af[4][4];
#pragma unroll
            for (int mt = 0; mt < 4; mt++)
                ldsm4(af[mt], abase + (uint32_t)(mt * 16 * A_STRIDE * 4 + k8 * 4));
#pragma unroll
            for (int nt = 0; nt < 4; nt++) {
                int c = wn * 32 + nt * 8 + grp;
                const float* bb = Bs + (k8 + tg) * B_STRIDE + c;
                uint32_t b0 = tf(bb[0]), b1 = tf(bb[4 * B_STRIDE]);
#pragma unroll
                for (int mt = 0; mt < 4; mt++)
                    mma8(acc[mt][nt], af[mt], b0, b1);
            }
        }
        __syncthreads();
        if (kt + 2 < NKT) { load_stage(kt + 2, b); CP_COMMIT(); }
    }

    // ---- epilogue ----
#pragma unroll
    for (int mt = 0; mt < 4; mt++) {
        int row0 = m0 + wm * 64 + mt * 16 + grp;
#pragma unroll
        for (int half = 0; half < 2; half++) {
            int r = row0 + half * 8;
            if (r < Mcnt) {
                int tok = (MODE == 0) ? g_perm[base + r] : r;
                float* orow = Out + (size_t)tok * DM + n0 + wn * 32;
#pragma unroll
                for (int nt = 0; nt < 4; nt++) {
                    float vx = acc[mt][nt][half * 2 + 0];
                    float vy = acc[mt][nt][half * 2 + 1];
                    float* o = orow + nt * 8 + tg * 2;
                    if (MODE == 0) {
                        *(float2*)o = make_float2(vx, vy);
                    } else {
                        float2 p = *(const float2*)o;
                        *(float2*)o = make_float2(p.x + vx, p.y + vy);
                    }
                }
            }
        }
    }
}

// ---------------- launch ----------------
extern "C" void kernel_launch(void* const* d_in, const int* in_sizes, int n_in,
                              void* d_out, int out_size) {
    const float* hidden   = (const float*)d_in[0];
    const float* router_w = (const float*)d_in[1];
    const float* gate_w   = (const float*)d_in[2];
    const float* up_w     = (const float*)d_in[3];
    const float* down_w   = (const float*)d_in[4];
    const float* sgate    = (const float*)d_in[5];
    const float* sup      = (const float*)d_in[6];
    const float* sdown    = (const float*)d_in[7];
    float* out = (float*)d_out;

    cudaFuncSetAttribute(gateup_mma,  cudaFuncAttributeMaxDynamicSharedMemorySize, GU_SMEM);
    cudaFuncSetAttribute(down_mma<0>, cudaFuncAttributeMaxDynamicSharedMemorySize, DN_SMEM);
    cudaFuncSetAttribute(down_mma<1>, cudaFuncAttributeMaxDynamicSharedMemorySize, DN_SMEM);

    init_kernel<<<1, 32>>>();
    router_kernel<<<T, 256>>>(hidden, router_w);
    scan_kernel<<<1, 32>>>();
    scatter_kernel<<<T / 256, 256>>>();

    dim3 gg(FF / BN, T / BM, NE + 1);   // z: 0..7 routed experts, 8 = shared expert
    gateup_mma<<<gg, 256, GU_SMEM>>>(gate_w, up_w, sgate, sup);

    dim3 dr(DM / BN, T / BM, NE);
    dim3 ds(DM / BN, T / BM, 1);
    down_mma<0><<<dr, 256, DN_SMEM>>>(down_w, out);    // scatter-overwrite (covers all tokens)
    down_mma<1><<<ds, 256, DN_SMEM>>>(sdown, out);     // accumulate shared expert
}

// round 10
// speedup vs baseline: 4.4137x; 1.4391x over previous
#include <cuda_runtime.h>
#include <cuda_fp16.h>
#include <math.h>
#include <stdint.h>

#define T 2048      // tokens
#define DM 2048     // model dim
#define FF 2048     // ffn dim
#define NE 8        // experts
#define BM 128
#define BN 128
#define BK 32
#define NKT (DM/BK)   // 64 k-stages

// smem layout
#define A_STRIDE_H 40                      // halfs per A row (32 + 8 pad): ldsm conflict-free
#define B_STRIDE 132                       // floats per B row: 2*132%32==8 -> k16 LDS conflict-free
#define A_BYTES (BM * A_STRIDE_H * 2)      // 10240
#define B_BYTES (BK * B_STRIDE * 4)        // 16896
#define GU_STAGE (A_BYTES + 2 * B_BYTES)   // 44032
#define GU_SMEM  (2 * GU_STAGE)            // 88064
#define DN_STAGE (A_BYTES + B_BYTES)       // 27136
#define DN_SMEM  (2 * DN_STAGE)            // 54272

// ---------------- scratch (device globals) ----------------
__device__ __align__(16) __half g_xs[(size_t)T * DM];   // fp16(x * score)
__device__ __align__(16) __half g_xr[(size_t)T * DM];   // fp16(x)
__device__ __align__(16) __half g_h [(size_t)T * FF];   // fp16(routed swiglu)
__device__ __align__(16) __half g_hs[(size_t)T * FF];   // fp16(shared swiglu)
__device__ int g_eidx[T];
__device__ int g_counts[NE];
__device__ int g_offsets[NE];
__device__ int g_cursor[NE];
__device__ int g_perm[T];

// ---------------- PTX helpers ----------------
__device__ __forceinline__ void cp16(uint32_t dst, const void* src, bool pred) {
    int bytes = pred ? 16 : 0;
    asm volatile("cp.async.cg.shared.global [%0], [%1], 16, %2;"
                 :: "r"(dst), "l"(src), "r"(bytes) : "memory");
}
#define CP_COMMIT() asm volatile("cp.async.commit_group;" ::: "memory")
#define CP_WAIT1()  asm volatile("cp.async.wait_group 1;" ::: "memory")
#define CP_WAIT0()  asm volatile("cp.async.wait_group 0;" ::: "memory")

__device__ __forceinline__ uint32_t smem_u32(const void* p) {
    uint32_t a;
    asm("{ .reg .u64 t; cvta.to.shared.u64 t, %1; cvt.u32.u64 %0, t; }" : "=r"(a) : "l"(p));
    return a;
}
// pack two f32 -> f16x2: lo = b, hi = a
__device__ __forceinline__ uint32_t h2(float hi, float lo) {
    uint32_t d;
    asm("cvt.rn.f16x2.f32 %0, %1, %2;" : "=r"(d) : "f"(hi), "f"(lo));
    return d;
}
// fp16 mma: m16n8k16, fp32 accum
__device__ __forceinline__ void mma16(float* c, const uint32_t* a, uint32_t b0, uint32_t b1) {
    asm volatile("mma.sync.aligned.m16n8k16.row.col.f32.f16.f16.f32 "
                 "{%0,%1,%2,%3}, {%4,%5,%6,%7}, {%8,%9}, {%0,%1,%2,%3};"
                 : "+f"(c[0]), "+f"(c[1]), "+f"(c[2]), "+f"(c[3])
                 : "r"(a[0]), "r"(a[1]), "r"(a[2]), "r"(a[3]), "r"(b0), "r"(b1));
}
// ldmatrix x4: full m16k16 f16 A fragment
__device__ __forceinline__ void ldsm4(uint32_t* r, uint32_t addr) {
    asm volatile("ldmatrix.sync.aligned.m8n8.x4.shared.b16 {%0,%1,%2,%3}, [%4];"
                 : "=r"(r[0]), "=r"(r[1]), "=r"(r[2]), "=r"(r[3]) : "r"(addr));
}

// ---------------- router / routing bookkeeping ----------------
__global__ void init_kernel() { if (threadIdx.x < NE) g_counts[threadIdx.x] = 0; }

__global__ void __launch_bounds__(256) router_kernel(const float* __restrict__ x,
                                                     const float* __restrict__ rw) {
    int t = blockIdx.x;
    const float* xr = x + (size_t)t * DM;
    float acc[NE];
#pragma unroll
    for (int e = 0; e < NE; e++) acc[e] = 0.f;
    for (int d = threadIdx.x; d < DM; d += 256) {
        float xv = xr[d];
        const float* r = rw + (size_t)d * NE;
#pragma unroll
        for (int e = 0; e < NE; e++) acc[e] = fmaf(xv, r[e], acc[e]);
    }
    __shared__ float sacc[8][NE];
    __shared__ float s_score;
    int lane = threadIdx.x & 31, warp = threadIdx.x >> 5;
#pragma unroll
    for (int e = 0; e < NE; e++) {
        float v = acc[e];
#pragma unroll
        for (int o = 16; o > 0; o >>= 1) v += __shfl_down_sync(0xffffffffu, v, o);
        if (lane == 0) sacc[warp][e] = v;
    }
    __syncthreads();
    if (threadIdx.x == 0) {
        float best = -INFINITY; int bi = 0;
#pragma unroll
        for (int e = 0; e < NE; e++) {
            float v = 0.f;
#pragma unroll
            for (int w = 0; w < 8; w++) v += sacc[w][e];
            if (v > best) { best = v; bi = e; }
        }
        s_score = 1.f / (1.f + expf(-best));
        g_eidx[t] = bi;
        atomicAdd(&g_counts[bi], 1);
    }
    __syncthreads();
    float sc = s_score;
    for (int d = threadIdx.x; d < DM; d += 256) {
        float xv = xr[d];
        g_xs[(size_t)t * DM + d] = __float2half_rn(xv * sc);
        g_xr[(size_t)t * DM + d] = __float2half_rn(xv);
    }
}

__global__ void scan_kernel() {
    if (threadIdx.x == 0) {
        int off = 0;
        for (int e = 0; e < NE; e++) { g_offsets[e] = off; g_cursor[e] = off; off += g_counts[e]; }
    }
}
__global__ void scatter_kernel() {
    int t = blockIdx.x * blockDim.x + threadIdx.x;
    if (t < T) { int e = g_eidx[t]; int pos = atomicAdd(&g_cursor[e], 1); g_perm[pos] = t; }
}

// ================= gate/up GEMM + fused SwiGLU (merged routed z<8 / shared z==8) =================
// 256 threads, 8 warps 2x4, warp tile 64x32 (mt=4, nt=4); fp16 A, on-the-fly fp16 B
__global__ void __launch_bounds__(256) gateup_mma(const float* __restrict__ Wg_all,
                                                  const float* __restrict__ Wu_all,
                                                  const float* __restrict__ Wsg,
                                                  const float* __restrict__ Wsu) {
    int e = blockIdx.z;
    bool sh = (e == NE);
    int Mcnt = sh ? T : g_counts[e];
    int base = sh ? 0 : g_offsets[e];
    int m0 = blockIdx.y * BM;
    if (m0 >= Mcnt) return;
    int n0 = blockIdx.x * BN;
    const __half* A = sh ? g_xr : g_xs;
    __half* Hout = sh ? g_hs : g_h;
    const float* Wg = sh ? Wsg : Wg_all + (size_t)e * DM * FF;
    const float* Wu = sh ? Wsu : Wu_all + (size_t)e * DM * FF;

    extern __shared__ char smem[];
    uint32_t sb = smem_u32(smem);
    int tid = threadIdx.x, wid = tid >> 5, lane = tid & 31;
    int wm = wid >> 2, wn = wid & 3;
    int grp = lane >> 2, tg = lane & 3;

    // ldmatrix per-lane A byte offset within tile: row=(lane&15)+wm*64(+mt*16), khalf=(lane>>4)*8
    uint32_t a_lm = (uint32_t)((((lane & 15) + wm * 64) * A_STRIDE_H + (lane >> 4) * 8) * 2);

    // ---- A copy: thread -> row tid/2, 16-half chunk q=(tid&1) (two cp16) ----
    const __half* arow = nullptr;
    uint32_t asoA;
    int q0 = (tid & 1) * 16;   // half offset
    {
        int r = tid >> 1;
        int gr = m0 + r;
        if (gr < Mcnt) {
            int tok = sh ? gr : g_perm[base + gr];
            arow = A + (size_t)tok * DM;
        }
        asoA = (uint32_t)((r * A_STRIDE_H + q0) * 2);
    }
    // ---- B copy: thread -> (k = tid/32 + 8i, n4 = tid%32) ----
    const float* bgp; const float* bup;
    uint32_t bso[4];
    {
        int n4 = tid & 31, kb = tid >> 5;
        bgp = Wg + (size_t)kb * FF + n0 + n4 * 4;
        bup = Wu + (size_t)kb * FF + n0 + n4 * 4;
#pragma unroll
        for (int i = 0; i < 4; i++)
            bso[i] = (uint32_t)(((kb + i * 8) * B_STRIDE + n4 * 4) * 4);
    }

    float accg[4][4][4], accu[4][4][4];
#pragma unroll
    for (int mt = 0; mt < 4; mt++)
#pragma unroll
        for (int nt = 0; nt < 4; nt++)
#pragma unroll
            for (int c = 0; c < 4; c++) { accg[mt][nt][c] = 0.f; accu[mt][nt][c] = 0.f; }

    auto load_stage = [&](int kt, int b) {
        uint32_t sA = sb + b * GU_STAGE;
        uint32_t sG = sA + A_BYTES;
        uint32_t sU = sG + B_BYTES;
        int k0 = kt * BK;
        cp16(sA + asoA,      arow ? (const void*)(arow + k0 + q0)     : (const void*)g_xs, arow != nullptr);
        cp16(sA + asoA + 16, arow ? (const void*)(arow + k0 + q0 + 8) : (const void*)g_xs, arow != nullptr);
#pragma unroll
        for (int i = 0; i < 4; i++) {
            cp16(sG + bso[i], bgp + (size_t)(k0 + i * 8) * FF, true);
            cp16(sU + bso[i], bup + (size_t)(k0 + i * 8) * FF, true);
        }
    };

    load_stage(0, 0); CP_COMMIT();
    load_stage(1, 1); CP_COMMIT();

    for (int kt = 0; kt < NKT; kt++) {
        if (kt == NKT - 1) { CP_WAIT0(); } else { CP_WAIT1(); }
        __syncthreads();
        int b = kt & 1;
        uint32_t sA = sb + b * GU_STAGE;
        const float* Bg = (const float*)(smem + b * GU_STAGE + A_BYTES);
        const float* Bu = (const float*)(smem + b * GU_STAGE + A_BYTES + B_BYTES);
        uint32_t abase = sA + a_lm;
#pragma unroll
        for (int kk = 0; kk < 2; kk++) {           // two k16 slices per BK=32 stage
            int kr = kk * 16;
            uint32_t af[4][4];
#pragma unroll
            for (int mt = 0; mt < 4; mt++)
                ldsm4(af[mt], abase + (uint32_t)((mt * 16 * A_STRIDE_H + kr) * 2));
#pragma unroll
            for (int nt = 0; nt < 4; nt++) {
                int c = wn * 32 + nt * 8 + grp;
                const float* gb = Bg + (kr + 2 * tg) * B_STRIDE + c;
                const float* ub = Bu + (kr + 2 * tg) * B_STRIDE + c;
                uint32_t g0 = h2(gb[B_STRIDE], gb[0]);
                uint32_t g1 = h2(gb[9 * B_STRIDE], gb[8 * B_STRIDE]);
                uint32_t u0 = h2(ub[B_STRIDE], ub[0]);
                uint32_t u1 = h2(ub[9 * B_STRIDE], ub[8 * B_STRIDE]);
#pragma unroll
                for (int mt = 0; mt < 4; mt++) {
                    mma16(accg[mt][nt], af[mt], g0, g1);
                    mma16(accu[mt][nt], af[mt], u0, u1);
                }
            }
        }
        __syncthreads();
        if (kt + 2 < NKT) { load_stage(kt + 2, b); CP_COMMIT(); }
    }

    // ---- epilogue: h = fp16(silu(g) * u) ----
#pragma unroll
    for (int mt = 0; mt < 4; mt++) {
        int row0 = m0 + wm * 64 + mt * 16 + grp;
#pragma unroll
        for (int half = 0; half < 2; half++) {
            int r = row0 + half * 8;
            if (r < Mcnt) {
                __half* orow = Hout + (size_t)(base + r) * FF + n0 + wn * 32;
#pragma unroll
                for (int nt = 0; nt < 4; nt++) {
                    float gx = accg[mt][nt][half * 2 + 0];
                    float gy = accg[mt][nt][half * 2 + 1];
                    float hx = gx / (1.f + expf(-gx)) * accu[mt][nt][half * 2 + 0];
                    float hy = gy / (1.f + expf(-gy)) * accu[mt][nt][half * 2 + 1];
                    *(__half2*)(orow + nt * 8 + tg * 2) = __floats2half2_rn(hx, hy);
                }
            }
        }
    }
}

// ================= down GEMM (fp16 mma) =================
template<int MODE>   // 0: routed scatter-overwrite, 1: shared accumulate
__global__ void __launch_bounds__(256, 2) down_mma(const float* __restrict__ W_all,
                                                   float* __restrict__ Out) {
    int e    = (MODE == 0) ? blockIdx.z : 0;
    int Mcnt = (MODE == 0) ? g_counts[e] : T;
    int base = (MODE == 0) ? g_offsets[e] : 0;
    int m0 = blockIdx.y * BM;
    if (m0 >= Mcnt) return;
    int n0 = blockIdx.x * BN;
    const __half* A = (MODE == 0) ? g_h : g_hs;
    const float* W = W_all + (size_t)e * FF * DM;

    extern __shared__ char smem[];
    uint32_t sb = smem_u32(smem);
    int tid = threadIdx.x, wid = tid >> 5, lane = tid & 31;
    int wm = wid >> 2, wn = wid & 3;
    int grp = lane >> 2, tg = lane & 3;

    uint32_t a_lm = (uint32_t)((((lane & 15) + wm * 64) * A_STRIDE_H + (lane >> 4) * 8) * 2);

    const __half* arow = nullptr;
    uint32_t asoA;
    int q0 = (tid & 1) * 16;
    {
        int r = tid >> 1;
        int gr = m0 + r;
        if (gr < Mcnt) arow = A + (size_t)(base + gr) * FF;
        asoA = (uint32_t)((r * A_STRIDE_H + q0) * 2);
    }
    const float* wp;
    uint32_t bso[4];
    {
        int n4 = tid & 31, kb = tid >> 5;
        wp = W + (size_t)kb * DM + n0 + n4 * 4;
#pragma unroll
        for (int i = 0; i < 4; i++)
            bso[i] = (uint32_t)(((kb + i * 8) * B_STRIDE + n4 * 4) * 4);
    }

    float acc[4][4][4];
#pragma unroll
    for (int mt = 0; mt < 4; mt++)
#pragma unroll
        for (int nt = 0; nt < 4; nt++)
#pragma unroll
            for (int c = 0; c < 4; c++) acc[mt][nt][c] = 0.f;

    auto load_stage = [&](int kt, int b) {
        uint32_t sA = sb + b * DN_STAGE;
        uint32_t sB = sA + A_BYTES;
        int k0 = kt * BK;
        cp16(sA + asoA,      arow ? (const void*)(arow + k0 + q0)     : (const void*)g_h, arow != nullptr);
        cp16(sA + asoA + 16, arow ? (const void*)(arow + k0 + q0 + 8) : (const void*)g_h, arow != nullptr);
#pragma unroll
        for (int i = 0; i < 4; i++)
            cp16(sB + bso[i], wp + (size_t)(k0 + i * 8) * DM, true);
    };

    load_stage(0, 0); CP_COMMIT();
    load_stage(1, 1); CP_COMMIT();

    for (int kt = 0; kt < NKT; kt++) {
        if (kt == NKT - 1) { CP_WAIT0(); } else { CP_WAIT1(); }
        __syncthreads();
        int b = kt & 1;
        uint32_t sA = sb + b * DN_STAGE;
        const float* Bs = (const float*)(smem + b * DN_STAGE + A_BYTES);
        uint32_t abase = sA + a_lm;
#pragma unroll
        for (int kk = 0; kk < 2; kk++) {
            int kr = kk * 16;
            uint32_t af[4][4];
#pragma unroll
            for (int mt = 0; mt < 4; mt++)
                ldsm4(af[mt], abase + (uint32_t)((mt * 16 * A_STRIDE_H + kr) * 2));
#pragma unroll
            for (int nt = 0; nt < 4; nt++) {
                int c = wn * 32 + nt * 8 + grp;
                const float* bb = Bs + (kr + 2 * tg) * B_STRIDE + c;
                uint32_t b0 = h2(bb[B_STRIDE], bb[0]);
                uint32_t b1 = h2(bb[9 * B_STRIDE], bb[8 * B_STRIDE]);
#pragma unroll
                for (int mt = 0; mt < 4; mt++)
                    mma16(acc[mt][nt], af[mt], b0, b1);
            }
        }
        __syncthreads();
        if (kt + 2 < NKT) { load_stage(kt + 2, b); CP_COMMIT(); }
    }

    // ---- epilogue ----
#pragma unroll
    for (int mt = 0; mt < 4; mt++) {
        int row0 = m0 + wm * 64 + mt * 16 + grp;
#pragma unroll
        for (int half = 0; half < 2; half++) {
            int r = row0 + half * 8;
            if (r < Mcnt) {
                int tok = (MODE == 0) ? g_perm[base + r] : r;
                float* orow = Out + (size_t)tok * DM + n0 + wn * 32;
#pragma unroll
                for (int nt = 0; nt < 4; nt++) {
                    float vx = acc[mt][nt][half * 2 + 0];
                    float vy = acc[mt][nt][half * 2 + 1];
                    float* o = orow + nt * 8 + tg * 2;
                    if (MODE == 0) {
                        *(float2*)o = make_float2(vx, vy);
                    } else {
                        float2 p = *(const float2*)o;
                        *(float2*)o = make_float2(p.x + vx, p.y + vy);
                    }
                }
            }
        }
    }
}

// ---------------- launch ----------------
extern "C" void kernel_launch(void* const* d_in, const int* in_sizes, int n_in,
                              void* d_out, int out_size) {
    const float* hidden   = (const float*)d_in[0];
    const float* router_w = (const float*)d_in[1];
    const float* gate_w   = (const float*)d_in[2];
    const float* up_w     = (const float*)d_in[3];
    const float* down_w   = (const float*)d_in[4];
    const float* sgate    = (const float*)d_in[5];
    const float* sup      = (const float*)d_in[6];
    const float* sdown    = (const float*)d_in[7];
    float* out = (float*)d_out;

    cudaFuncSetAttribute(gateup_mma,  cudaFuncAttributeMaxDynamicSharedMemorySize, GU_SMEM);
    cudaFuncSetAttribute(down_mma<0>, cudaFuncAttributeMaxDynamicSharedMemorySize, DN_SMEM);
    cudaFuncSetAttribute(down_mma<1>, cudaFuncAttributeMaxDynamicSharedMemorySize, DN_SMEM);

    init_kernel<<<1, 32>>>();
    router_kernel<<<T, 256>>>(hidden, router_w);
    scan_kernel<<<1, 32>>>();
    scatter_kernel<<<T / 256, 256>>>();

    dim3 gg(FF / BN, T / BM, NE + 1);   // z: 0..7 routed experts, 8 = shared expert
    gateup_mma<<<gg, 256, GU_SMEM>>>(gate_w, up_w, sgate, sup);

    dim3 dr(DM / BN, T / BM, NE);
    dim3 ds(DM / BN, T / BM, 1);
    down_mma<0><<<dr, 256, DN_SMEM>>>(down_w, out);    // scatter-overwrite (covers all tokens)
    down_mma<1><<<ds, 256, DN_SMEM>>>(sdown, out);     // accumulate shared expert
}

// round 11
// speedup vs baseline: 4.6307x; 1.0492x over previous
#include <cuda_runtime.h>
#include <cuda_fp16.h>
#include <math.h>
#include <stdint.h>

#define T 2048      // tokens
#define DM 2048     // model dim
#define FF 2048     // ffn dim
#define NE 8        // experts
#define BM 128
#define BN 128
#define BK 32
#define NKT (DM/BK)   // 64 k-stages

// smem layout
#define A_STRIDE_H 40                      // halfs per A row (32+8 pad): ldsm conflict-free
#define B_STRIDE_H 136                     // halfs per B row (128+8 pad): 272B rows -> ldsm.trans conflict-free
#define A_BYTES (BM * A_STRIDE_H * 2)      // 10240
#define B_BYTES_H (BK * B_STRIDE_H * 2)    // 8704
#define GU_STAGE (A_BYTES + 2 * B_BYTES_H) // 27648
#define GU_SMEM  (2 * GU_STAGE)            // 55296
#define DN_STAGE (A_BYTES + B_BYTES_H)     // 18944
#define DN_SMEM  (2 * DN_STAGE)            // 37888

// ---------------- scratch (device globals) ----------------
__device__ __align__(16) __half g_xs[(size_t)T * DM];   // fp16(x * score)
__device__ __align__(16) __half g_xr[(size_t)T * DM];   // fp16(x)
__device__ __align__(16) __half g_h [(size_t)T * FF];   // fp16(routed swiglu)
__device__ __align__(16) __half g_hs[(size_t)T * FF];   // fp16(shared swiglu)
// fp16 weights (pre-converted each call; bit-identical to per-use rounding)
__device__ __align__(16) __half w_g [(size_t)NE * DM * FF];
__device__ __align__(16) __half w_u [(size_t)NE * DM * FF];
__device__ __align__(16) __half w_d [(size_t)NE * FF * DM];
__device__ __align__(16) __half w_sg[(size_t)DM * FF];
__device__ __align__(16) __half w_su[(size_t)DM * FF];
__device__ __align__(16) __half w_sd[(size_t)FF * DM];
__device__ int g_eidx[T];
__device__ int g_counts[NE];
__device__ int g_offsets[NE];
__device__ int g_cursor[NE];
__device__ int g_perm[T];

// ---------------- PTX helpers ----------------
__device__ __forceinline__ void cp16(uint32_t dst, const void* src, bool pred) {
    int bytes = pred ? 16 : 0;
    asm volatile("cp.async.cg.shared.global [%0], [%1], 16, %2;"
                 :: "r"(dst), "l"(src), "r"(bytes) : "memory");
}
#define CP_COMMIT() asm volatile("cp.async.commit_group;" ::: "memory")
#define CP_WAIT1()  asm volatile("cp.async.wait_group 1;" ::: "memory")
#define CP_WAIT0()  asm volatile("cp.async.wait_group 0;" ::: "memory")

__device__ __forceinline__ uint32_t smem_u32(const void* p) {
    uint32_t a;
    asm("{ .reg .u64 t; cvta.to.shared.u64 t, %1; cvt.u32.u64 %0, t; }" : "=r"(a) : "l"(p));
    return a;
}
// fp16 mma: m16n8k16, fp32 accum
__device__ __forceinline__ void mma16(float* c, const uint32_t* a, uint32_t b0, uint32_t b1) {
    asm volatile("mma.sync.aligned.m16n8k16.row.col.f32.f16.f16.f32 "
                 "{%0,%1,%2,%3}, {%4,%5,%6,%7}, {%8,%9}, {%0,%1,%2,%3};"
                 : "+f"(c[0]), "+f"(c[1]), "+f"(c[2]), "+f"(c[3])
                 : "r"(a[0]), "r"(a[1]), "r"(a[2]), "r"(a[3]), "r"(b0), "r"(b1));
}
// ldmatrix x4 (A fragments, row-major)
__device__ __forceinline__ void ldsm4(uint32_t* r, uint32_t addr) {
    asm volatile("ldmatrix.sync.aligned.m8n8.x4.shared.b16 {%0,%1,%2,%3}, [%4];"
                 : "=r"(r[0]), "=r"(r[1]), "=r"(r[2]), "=r"(r[3]) : "r"(addr));
}
// ldmatrix x4 trans (B fragments from [k][n] row-major smem)
__device__ __forceinline__ void ldsm4t(uint32_t* r, uint32_t addr) {
    asm volatile("ldmatrix.sync.aligned.m8n8.x4.trans.shared.b16 {%0,%1,%2,%3}, [%4];"
                 : "=r"(r[0]), "=r"(r[1]), "=r"(r[2]), "=r"(r[3]) : "r"(addr));
}

// ---------------- weight conversion fp32 -> fp16 ----------------
__global__ void __launch_bounds__(256) convert_kernel(const float4* __restrict__ src,
                                                      uint2* __restrict__ dst, int n4) {
    int i = blockIdx.x * blockDim.x + threadIdx.x;
    if (i < n4) {
        float4 v = src[i];
        __half2 a = __floats2half2_rn(v.x, v.y);
        __half2 b = __floats2half2_rn(v.z, v.w);
        uint2 o;
        o.x = *(uint32_t*)&a;
        o.y = *(uint32_t*)&b;
        dst[i] = o;
    }
}

// ---------------- router / routing bookkeeping ----------------
__global__ void init_kernel() { if (threadIdx.x < NE) g_counts[threadIdx.x] = 0; }

__global__ void __launch_bounds__(256) router_kernel(const float* __restrict__ x,
                                                     const float* __restrict__ rw) {
    int t = blockIdx.x;
    const float* xr = x + (size_t)t * DM;
    float acc[NE];
#pragma unroll
    for (int e = 0; e < NE; e++) acc[e] = 0.f;
    for (int d = threadIdx.x; d < DM; d += 256) {
        float xv = xr[d];
        const float* r = rw + (size_t)d * NE;
#pragma unroll
        for (int e = 0; e < NE; e++) acc[e] = fmaf(xv, r[e], acc[e]);
    }
    __shared__ float sacc[8][NE];
    __shared__ float s_score;
    int lane = threadIdx.x & 31, warp = threadIdx.x >> 5;
#pragma unroll
    for (int e = 0; e < NE; e++) {
        float v = acc[e];
#pragma unroll
        for (int o = 16; o > 0; o >>= 1) v += __shfl_down_sync(0xffffffffu, v, o);
        if (lane == 0) sacc[warp][e] = v;
    }
    __syncthreads();
    if (threadIdx.x == 0) {
        float best = -INFINITY; int bi = 0;
#pragma unroll
        for (int e = 0; e < NE; e++) {
            float v = 0.f;
#pragma unroll
            for (int w = 0; w < 8; w++) v += sacc[w][e];
            if (v > best) { best = v; bi = e; }
        }
        s_score = 1.f / (1.f + expf(-best));
        g_eidx[t] = bi;
        atomicAdd(&g_counts[bi], 1);
    }
    __syncthreads();
    float sc = s_score;
    for (int d = threadIdx.x; d < DM; d += 256) {
        float xv = xr[d];
        g_xs[(size_t)t * DM + d] = __float2half_rn(xv * sc);
        g_xr[(size_t)t * DM + d] = __float2half_rn(xv);
    }
}

__global__ void scan_kernel() {
    if (threadIdx.x == 0) {
        int off = 0;
        for (int e = 0; e < NE; e++) { g_offsets[e] = off; g_cursor[e] = off; off += g_counts[e]; }
    }
}
__global__ void scatter_kernel() {
    int t = blockIdx.x * blockDim.x + threadIdx.x;
    if (t < T) { int e = g_eidx[t]; int pos = atomicAdd(&g_cursor[e], 1); g_perm[pos] = t; }
}

// ================= gate/up GEMM + fused SwiGLU (merged routed z<8 / shared z==8) =================
// 256 threads, 8 warps 2x4, warp tile 64x32 (mt=4, nt=4); all-fp16 operands
__global__ void __launch_bounds__(256) gateup_mma() {
    int e = blockIdx.z;
    bool sh = (e == NE);
    int Mcnt = sh ? T : g_counts[e];
    int base = sh ? 0 : g_offsets[e];
    int m0 = blockIdx.y * BM;
    if (m0 >= Mcnt) return;
    int n0 = blockIdx.x * BN;
    const __half* A = sh ? g_xr : g_xs;
    __half* Hout = sh ? g_hs : g_h;
    const __half* Wg = sh ? w_sg : w_g + (size_t)e * DM * FF;
    const __half* Wu = sh ? w_su : w_u + (size_t)e * DM * FF;

    extern __shared__ char smem[];
    uint32_t sb = smem_u32(smem);
    int tid = threadIdx.x, wid = tid >> 5, lane = tid & 31;
    int wm = wid >> 2, wn = wid & 3;
    int grp = lane >> 2, tg = lane & 3;

    // ldmatrix A per-lane byte offset: row=(lane&15)+wm*64(+mt*16), khalf=(lane>>4)*8
    uint32_t a_lm = (uint32_t)((((lane & 15) + wm * 64) * A_STRIDE_H + (lane >> 4) * 8) * 2);
    // ldmatrix.trans B per-lane byte offset: k=(lane&7)+((lane>>3)&1)*8, n=(lane>>4)*8 (+wn*32+p*16)
    uint32_t b_lm = (uint32_t)(((((lane & 7) + ((lane >> 3) & 1) * 8) * B_STRIDE_H)
                               + wn * 32 + (lane >> 4) * 8) * 2);

    // ---- A copy: thread -> row tid/2, 16-half chunk (tid&1) ----
    const __half* arow = nullptr;
    uint32_t asoA;
    int q0 = (tid & 1) * 16;
    {
        int r = tid >> 1;
        int gr = m0 + r;
        if (gr < Mcnt) {
            int tok = sh ? gr : g_perm[base + gr];
            arow = A + (size_t)tok * DM;
        }
        asoA = (uint32_t)((r * A_STRIDE_H + q0) * 2);
    }
    // ---- B copy: thread -> (k = tid/16 + 16i, n8 = tid%16), i=0..1, per matrix ----
    const __half* bgp; const __half* bup;
    uint32_t bso[2];
    {
        int n8 = tid & 15, kb = tid >> 4;   // kb 0..15
        bgp = Wg + (size_t)kb * FF + n0 + n8 * 8;
        bup = Wu + (size_t)kb * FF + n0 + n8 * 8;
#pragma unroll
        for (int i = 0; i < 2; i++)
            bso[i] = (uint32_t)(((kb + i * 16) * B_STRIDE_H + n8 * 8) * 2);
    }

    float accg[4][4][4], accu[4][4][4];
#pragma unroll
    for (int mt = 0; mt < 4; mt++)
#pragma unroll
        for (int nt = 0; nt < 4; nt++)
#pragma unroll
            for (int c = 0; c < 4; c++) { accg[mt][nt][c] = 0.f; accu[mt][nt][c] = 0.f; }

    auto load_stage = [&](int kt, int b) {
        uint32_t sA = sb + b * GU_STAGE;
        uint32_t sG = sA + A_BYTES;
        uint32_t sU = sG + B_BYTES_H;
        int k0 = kt * BK;
        cp16(sA + asoA,      arow ? (const void*)(arow + k0 + q0)     : (const void*)g_xs, arow != nullptr);
        cp16(sA + asoA + 16, arow ? (const void*)(arow + k0 + q0 + 8) : (const void*)g_xs, arow != nullptr);
#pragma unroll
        for (int i = 0; i < 2; i++) {
            cp16(sG + bso[i], bgp + (size_t)(k0 + i * 16) * FF, true);
            cp16(sU + bso[i], bup + (size_t)(k0 + i * 16) * FF, true);
        }
    };

    load_stage(0, 0); CP_COMMIT();
    load_stage(1, 1); CP_COMMIT();

    for (int kt = 0; kt < NKT; kt++) {
        if (kt == NKT - 1) { CP_WAIT0(); } else { CP_WAIT1(); }
        __syncthreads();
        int b = kt & 1;
        uint32_t sA = sb + b * GU_STAGE;
        uint32_t sG = sA + A_BYTES;
        uint32_t sU = sG + B_BYTES_H;
        uint32_t abase = sA + a_lm;
        uint32_t gbase = sG + b_lm;
        uint32_t ubase = sU + b_lm;
#pragma unroll
        for (int kk = 0; kk < 2; kk++) {            // two k16 slices per BK=32 stage
            int kr = kk * 16;
            uint32_t af[4][4];
#pragma unroll
            for (int mt = 0; mt < 4; mt++)
                ldsm4(af[mt], abase + (uint32_t)((mt * 16 * A_STRIDE_H + kr) * 2));
            uint32_t bg[2][4], bu[2][4];
#pragma unroll
            for (int p = 0; p < 2; p++) {
                ldsm4t(bg[p], gbase + (uint32_t)((kr * B_STRIDE_H + p * 16) * 2));
                ldsm4t(bu[p], ubase + (uint32_t)((kr * B_STRIDE_H + p * 16) * 2));
            }
#pragma unroll
            for (int p = 0; p < 2; p++)
#pragma unroll
                for (int mt = 0; mt < 4; mt++) {
                    mma16(accg[mt][2 * p + 0], af[mt], bg[p][0], bg[p][1]);
                    mma16(accg[mt][2 * p + 1], af[mt], bg[p][2], bg[p][3]);
                    mma16(accu[mt][2 * p + 0], af[mt], bu[p][0], bu[p][1]);
                    mma16(accu[mt][2 * p + 1], af[mt], bu[p][2], bu[p][3]);
                }
        }
        __syncthreads();
        if (kt + 2 < NKT) { load_stage(kt + 2, b); CP_COMMIT(); }
    }

    // ---- epilogue: h = fp16(silu(g) * u) ----
#pragma unroll
    for (int mt = 0; mt < 4; mt++) {
        int row0 = m0 + wm * 64 + mt * 16 + grp;
#pragma unroll
        for (int half = 0; half < 2; half++) {
            int r = row0 + half * 8;
            if (r < Mcnt) {
                __half* orow = Hout + (size_t)(base + r) * FF + n0 + wn * 32;
#pragma unroll
                for (int nt = 0; nt < 4; nt++) {
                    float gx = accg[mt][nt][half * 2 + 0];
                    float gy = accg[mt][nt][half * 2 + 1];
                    float hx = gx / (1.f + expf(-gx)) * accu[mt][nt][half * 2 + 0];
                    float hy = gy / (1.f + expf(-gy)) * accu[mt][nt][half * 2 + 1];
                    *(__half2*)(orow + nt * 8 + tg * 2) = __floats2half2_rn(hx, hy);
                }
            }
        }
    }
}

// ================= down GEMM (fp16 mma) =================
template<int MODE>   // 0: routed scatter-overwrite, 1: shared accumulate
__global__ void __launch_bounds__(256, 2) down_mma(float* __restrict__ Out) {
    int e    = (MODE == 0) ? blockIdx.z : 0;
    int Mcnt = (MODE == 0) ? g_counts[e] : T;
    int base = (MODE == 0) ? g_offsets[e] : 0;
    int m0 = blockIdx.y * BM;
    if (m0 >= Mcnt) return;
    int n0 = blockIdx.x * BN;
    const __half* A = (MODE == 0) ? g_h : g_hs;
    const __half* W = (MODE == 0) ? (w_d + (size_t)e * FF * DM) : w_sd;

    extern __shared__ char smem[];
    uint32_t sb = smem_u32(smem);
    int tid = threadIdx.x, wid = tid >> 5, lane = tid & 31;
    int wm = wid >> 2, wn = wid & 3;
    int grp = lane >> 2, tg = lane & 3;

    uint32_t a_lm = (uint32_t)((((lane & 15) + wm * 64) * A_STRIDE_H + (lane >> 4) * 8) * 2);
    uint32_t b_lm = (uint32_t)(((((lane & 7) + ((lane >> 3) & 1) * 8) * B_STRIDE_H)
                               + wn * 32 + (lane >> 4) * 8) * 2);

    const __half* arow = nullptr;
    uint32_t asoA;
    int q0 = (tid & 1) * 16;
    {
        int r = tid >> 1;
        int gr = m0 + r;
        if (gr < Mcnt) arow = A + (size_t)(base + gr) * FF;
        asoA = (uint32_t)((r * A_STRIDE_H + q0) * 2);
    }
    const __half* wp;
    uint32_t bso[2];
    {
        int n8 = tid & 15, kb = tid >> 4;
        wp = W + (size_t)kb * DM + n0 + n8 * 8;
#pragma unroll
        for (int i = 0; i < 2; i++)
            bso[i] = (uint32_t)(((kb + i * 16) * B_STRIDE_H + n8 * 8) * 2);
    }

    float acc[4][4][4];
#pragma unroll
    for (int mt = 0; mt < 4; mt++)
#pragma unroll
        for (int nt = 0; nt < 4; nt++)
#pragma unroll
            for (int c = 0; c < 4; c++) acc[mt][nt][c] = 0.f;

    auto load_stage = [&](int kt, int b) {
        uint32_t sA = sb + b * DN_STAGE;
        uint32_t sB = sA + A_BYTES;
        int k0 = kt * BK;
        cp16(sA + asoA,      arow ? (const void*)(arow + k0 + q0)     : (const void*)g_h, arow != nullptr);
        cp16(sA + asoA + 16, arow ? (const void*)(arow + k0 + q0 + 8) : (const void*)g_h, arow != nullptr);
#pragma unroll
        for (int i = 0; i < 2; i++)
            cp16(sB + bso[i], wp + (size_t)(k0 + i * 16) * DM, true);
    };

    load_stage(0, 0); CP_COMMIT();
    load_stage(1, 1); CP_COMMIT();

    for (int kt = 0; kt < NKT; kt++) {
        if (kt == NKT - 1) { CP_WAIT0(); } else { CP_WAIT1(); }
        __syncthreads();
        int b = kt & 1;
        uint32_t sA = sb + b * DN_STAGE;
        uint32_t sB = sA + A_BYTES;
        uint32_t abase = sA + a_lm;
        uint32_t bbase = sB + b_lm;
#pragma unroll
        for (int kk = 0; kk < 2; kk++) {
            int kr = kk * 16;
            uint32_t af[4][4];
#pragma unroll
            for (int mt = 0; mt < 4; mt++)
                ldsm4(af[mt], abase + (uint32_t)((mt * 16 * A_STRIDE_H + kr) * 2));
            uint32_t bf[2][4];
#pragma unroll
            for (int p = 0; p < 2; p++)
                ldsm4t(bf[p], bbase + (uint32_t)((kr * B_STRIDE_H + p * 16) * 2));
#pragma unroll
            for (int p = 0; p < 2; p++)
#pragma unroll
                for (int mt = 0; mt < 4; mt++) {
                    mma16(acc[mt][2 * p + 0], af[mt], bf[p][0], bf[p][1]);
                    mma16(acc[mt][2 * p + 1], af[mt], bf[p][2], bf[p][3]);
                }
        }
        __syncthreads();
        if (kt + 2 < NKT) { load_stage(kt + 2, b); CP_COMMIT(); }
    }

    // ---- epilogue ----
#pragma unroll
    for (int mt = 0; mt < 4; mt++) {
        int row0 = m0 + wm * 64 + mt * 16 + grp;
#pragma unroll
        for (int half = 0; half < 2; half++) {
            int r = row0 + half * 8;
            if (r < Mcnt) {
                int tok = (MODE == 0) ? g_perm[base + r] : r;
                float* orow = Out + (size_t)tok * DM + n0 + wn * 32;
#pragma unroll
                for (int nt = 0; nt < 4; nt++) {
                    float vx = acc[mt][nt][half * 2 + 0];
                    float vy = acc[mt][nt][half * 2 + 1];
                    float* o = orow + nt * 8 + tg * 2;
                    if (MODE == 0) {
                        *(float2*)o = make_float2(vx, vy);
                    } else {
                        float2 p = *(const float2*)o;
                        *(float2*)o = make_float2(p.x + vx, p.y + vy);
                    }
                }
            }
        }
    }
}

// ---------------- launch ----------------
extern "C" void kernel_launch(void* const* d_in, const int* in_sizes, int n_in,
                              void* d_out, int out_size) {
    const float* hidden   = (const float*)d_in[0];
    const float* router_w = (const float*)d_in[1];
    const float* gate_w   = (const float*)d_in[2];
    const float* up_w     = (const float*)d_in[3];
    const float* down_w   = (const float*)d_in[4];
    const float* sgate    = (const float*)d_in[5];
    const float* sup      = (const float*)d_in[6];
    const float* sdown    = (const float*)d_in[7];
    float* out = (float*)d_out;

    cudaFuncSetAttribute(gateup_mma,  cudaFuncAttributeMaxDynamicSharedMemorySize, GU_SMEM);
    cudaFuncSetAttribute(down_mma<0>, cudaFuncAttributeMaxDynamicSharedMemorySize, DN_SMEM);
    cudaFuncSetAttribute(down_mma<1>, cudaFuncAttributeMaxDynamicSharedMemorySize, DN_SMEM);

    // fp16 weight scratch addresses (device symbols)
    __half *dwg, *dwu, *dwd, *dsg, *dsu, *dsd;
    cudaGetSymbolAddress((void**)&dwg, w_g);
    cudaGetSymbolAddress((void**)&dwu, w_u);
    cudaGetSymbolAddress((void**)&dwd, w_d);
    cudaGetSymbolAddress((void**)&dsg, w_sg);
    cudaGetSymbolAddress((void**)&dsu, w_su);
    cudaGetSymbolAddress((void**)&dsd, w_sd);

    const int nBig = NE * DM * FF / 4;   // float4 count per big weight
    const int nSml = DM * FF / 4;
    convert_kernel<<<(nBig + 255) / 256, 256>>>((const float4*)gate_w, (uint2*)dwg, nBig);
    convert_kernel<<<(nBig + 255) / 256, 256>>>((const float4*)up_w,   (uint2*)dwu, nBig);
    convert_kernel<<<(nBig + 255) / 256, 256>>>((const float4*)down_w, (uint2*)dwd, nBig);
    convert_kernel<<<(nSml + 255) / 256, 256>>>((const float4*)sgate,  (uint2*)dsg, nSml);
    convert_kernel<<<(nSml + 255) / 256, 256>>>((const float4*)sup,    (uint2*)dsu, nSml);
    convert_kernel<<<(nSml + 255) / 256, 256>>>((const float4*)sdown,  (uint2*)dsd, nSml);

    init_kernel<<<1, 32>>>();
    router_kernel<<<T, 256>>>(hidden, router_w);
    scan_kernel<<<1, 32>>>();
    scatter_kernel<<<T / 256, 256>>>();

    dim3 gg(FF / BN, T / BM, NE + 1);   // z: 0..7 routed experts, 8 = shared expert
    gateup_mma<<<gg, 256, GU_SMEM>>>();

    dim3 dr(DM / BN, T / BM, NE);
    dim3 ds(DM / BN, T / BM, 1);
    down_mma<0><<<dr, 256, DN_SMEM>>>(out);    // scatter-overwrite (covers all tokens)
    down_mma<1><<<ds, 256, DN_SMEM>>>(out);    // accumulate shared expert
}

// round 13
// speedup vs baseline: 5.0593x; 1.0926x over previous
#include <cuda_runtime.h>
#include <cuda_fp16.h>
#include <math.h>
#include <stdint.h>

#define T 2048      // tokens
#define DM 2048     // model dim
#define FF 2048     // ffn dim
#define NE 8        // experts
#define BM 128
#define BN 128
#define BK 32
#define NKT (DM/BK)   // 64 k-stages

// smem layout (all fp16)
#define A_STRIDE_H 40                      // halfs per A row (32+8 pad): ldsm conflict-free
#define B_STRIDE_H 136                     // halfs per B row (128+8 pad): ldsm.trans conflict-free
#define A_BYTES (BM * A_STRIDE_H * 2)      // 10240
#define B_BYTES_H (BK * B_STRIDE_H * 2)    // 8704
#define GU_STAGE (A_BYTES + 2 * B_BYTES_H) // 27648
#define GU_SMEM  (2 * GU_STAGE)            // 55296
#define DN_STAGE (A_BYTES + B_BYTES_H)     // 18944
#define DN_SMEM  (2 * DN_STAGE)            // 37888

// ---------------- scratch (device globals) ----------------
__device__ __align__(16) __half g_xs[(size_t)T * DM];   // fp16(x * score)
__device__ __align__(16) __half g_xr[(size_t)T * DM];   // fp16(x)
__device__ __align__(16) __half g_h [(size_t)T * FF];   // fp16(routed swiglu)
__device__ __align__(16) __half g_hs[(size_t)T * FF];   // fp16(shared swiglu)
__device__ int g_eidx[T];
__device__ int g_counts[NE];
__device__ int g_offsets[NE];
__device__ int g_cursor[NE];
__device__ int g_perm[T];

// ---------------- PTX helpers ----------------
__device__ __forceinline__ void cp16(uint32_t dst, const void* src, bool pred) {
    int bytes = pred ? 16 : 0;
    asm volatile("cp.async.cg.shared.global [%0], [%1], 16, %2;"
                 :: "r"(dst), "l"(src), "r"(bytes) : "memory");
}
#define CP_COMMIT() asm volatile("cp.async.commit_group;" ::: "memory")
#define CP_WAIT0()  asm volatile("cp.async.wait_group 0;" ::: "memory")

__device__ __forceinline__ uint32_t smem_u32(const void* p) {
    uint32_t a;
    asm("{ .reg .u64 t; cvta.to.shared.u64 t, %1; cvt.u32.u64 %0, t; }" : "=r"(a) : "l"(p));
    return a;
}
// pack two f32 -> f16x2 (lo in low half)
__device__ __forceinline__ uint32_t h2(float hi, float lo) {
    uint32_t d;
    asm("cvt.rn.f16x2.f32 %0, %1, %2;" : "=r"(d) : "f"(hi), "f"(lo));
    return d;
}
// fp16 mma: m16n8k16, fp32 accum
__device__ __forceinline__ void mma16(float* c, const uint32_t* a, uint32_t b0, uint32_t b1) {
    asm volatile("mma.sync.aligned.m16n8k16.row.col.f32.f16.f16.f32 "
                 "{%0,%1,%2,%3}, {%4,%5,%6,%7}, {%8,%9}, {%0,%1,%2,%3};"
                 : "+f"(c[0]), "+f"(c[1]), "+f"(c[2]), "+f"(c[3])
                 : "r"(a[0]), "r"(a[1]), "r"(a[2]), "r"(a[3]), "r"(b0), "r"(b1));
}
__device__ __forceinline__ void ldsm4(uint32_t* r, uint32_t addr) {
    asm volatile("ldmatrix.sync.aligned.m8n8.x4.shared.b16 {%0,%1,%2,%3}, [%4];"
                 : "=r"(r[0]), "=r"(r[1]), "=r"(r[2]), "=r"(r[3]) : "r"(addr));
}
__device__ __forceinline__ void ldsm4t(uint32_t* r, uint32_t addr) {
    asm volatile("ldmatrix.sync.aligned.m8n8.x4.trans.shared.b16 {%0,%1,%2,%3}, [%4];"
                 : "=r"(r[0]), "=r"(r[1]), "=r"(r[2]), "=r"(r[3]) : "r"(addr));
}
// pack 8 fp32 (two float4) into 8 fp16 (uint4)
__device__ __forceinline__ uint4 pack8(float4 v0, float4 v1) {
    uint4 o;
    o.x = h2(v0.y, v0.x); o.y = h2(v0.w, v0.z);
    o.z = h2(v1.y, v1.x); o.w = h2(v1.w, v1.z);
    return o;
}

// ---------------- router / routing bookkeeping ----------------
__global__ void init_kernel() { if (threadIdx.x < NE) g_counts[threadIdx.x] = 0; }

__global__ void __launch_bounds__(256) router_kernel(const float* __restrict__ x,
                                                     const float* __restrict__ rw) {
    int t = blockIdx.x;
    const float* xr = x + (size_t)t * DM;
    float acc[NE];
#pragma unroll
    for (int e = 0; e < NE; e++) acc[e] = 0.f;
    for (int d = threadIdx.x; d < DM; d += 256) {
        float xv = xr[d];
        const float* r = rw + (size_t)d * NE;
#pragma unroll
        for (int e = 0; e < NE; e++) acc[e] = fmaf(xv, r[e], acc[e]);
    }
    __shared__ float sacc[8][NE];
    __shared__ float s_score;
    int lane = threadIdx.x & 31, warp = threadIdx.x >> 5;
#pragma unroll
    for (int e = 0; e < NE; e++) {
        float v = acc[e];
#pragma unroll
        for (int o = 16; o > 0; o >>= 1) v += __shfl_down_sync(0xffffffffu, v, o);
        if (lane == 0) sacc[warp][e] = v;
    }
    __syncthreads();
    if (threadIdx.x == 0) {
        float best = -INFINITY; int bi = 0;
#pragma unroll
        for (int e = 0; e < NE; e++) {
            float v = 0.f;
#pragma unroll
            for (int w = 0; w < 8; w++) v += sacc[w][e];
            if (v > best) { best = v; bi = e; }
        }
        s_score = 1.f / (1.f + expf(-best));
        g_eidx[t] = bi;
        atomicAdd(&g_counts[bi], 1);
    }
    __syncthreads();
    float sc = s_score;
    for (int d = threadIdx.x; d < DM; d += 256) {
        float xv = xr[d];
        g_xs[(size_t)t * DM + d] = __float2half_rn(xv * sc);
        g_xr[(size_t)t * DM + d] = __float2half_rn(xv);
    }
}

__global__ void scan_kernel() {
    if (threadIdx.x == 0) {
        int off = 0;
        for (int e = 0; e < NE; e++) { g_offsets[e] = off; g_cursor[e] = off; off += g_counts[e]; }
    }
}
__global__ void scatter_kernel() {
    int t = blockIdx.x * blockDim.x + threadIdx.x;
    if (t < T) { int e = g_eidx[t]; int pos = atomicAdd(&g_cursor[e], 1); g_perm[pos] = t; }
}

// ================= gate/up GEMM + fused SwiGLU (merged routed z<8 / shared z==8) =================
// 256 threads, 8 warps 2x4, warp tile 64x32; fp32 weights converted in-register to fp16 smem
__global__ void __launch_bounds__(256) gateup_mma(const float* __restrict__ Wg_all,
                                                  const float* __restrict__ Wu_all,
                                                  const float* __restrict__ Wsg,
                                                  const float* __restrict__ Wsu) {
    int e = blockIdx.z;
    bool sh = (e == NE);
    int Mcnt = sh ? T : g_counts[e];
    int base = sh ? 0 : g_offsets[e];
    int m0 = blockIdx.y * BM;
    if (m0 >= Mcnt) return;
    int n0 = blockIdx.x * BN;
    const __half* A = sh ? g_xr : g_xs;
    __half* Hout = sh ? g_hs : g_h;
    const float* Wg = sh ? Wsg : Wg_all + (size_t)e * DM * FF;
    const float* Wu = sh ? Wsu : Wu_all + (size_t)e * DM * FF;

    extern __shared__ char smem[];
    uint32_t sb = smem_u32(smem);
    int tid = threadIdx.x, wid = tid >> 5, lane = tid & 31;
    int wm = wid >> 2, wn = wid & 3;
    int grp = lane >> 2, tg = lane & 3;

    uint32_t a_lm = (uint32_t)((((lane & 15) + wm * 64) * A_STRIDE_H + (lane >> 4) * 8) * 2);
    uint32_t b_lm = (uint32_t)(((((lane & 7) + ((lane >> 3) & 1) * 8) * B_STRIDE_H)
                               + wn * 32 + (lane >> 4) * 8) * 2);

    // ---- A copy (cp.async fp16): row tid/2, 16-half chunk (tid&1) ----
    const __half* arow = nullptr;
    uint32_t asoA;
    int q0 = (tid & 1) * 16;
    {
        int r = tid >> 1;
        int gr = m0 + r;
        if (gr < Mcnt) {
            int tok = sh ? gr : g_perm[base + gr];
            arow = A + (size_t)tok * DM;
        }
        asoA = (uint32_t)((r * A_STRIDE_H + q0) * 2);
    }
    // ---- B load/convert mapping: n8 = tid&15 (8-float chunk), kb = tid>>4 -> rows kb, kb+16 ----
    int n8 = tid & 15, kb = tid >> 4;
    const float* bgp = Wg + (size_t)kb * FF + n0 + n8 * 8;
    const float* bup = Wu + (size_t)kb * FF + n0 + n8 * 8;
    uint32_t bsts[2];
#pragma unroll
    for (int i = 0; i < 2; i++)
        bsts[i] = (uint32_t)(((kb + i * 16) * B_STRIDE_H + n8 * 8) * 2);

    float accg[4][4][4], accu[4][4][4];
#pragma unroll
    for (int mt = 0; mt < 4; mt++)
#pragma unroll
        for (int nt = 0; nt < 4; nt++)
#pragma unroll
            for (int c = 0; c < 4; c++) { accg[mt][nt][c] = 0.f; accu[mt][nt][c] = 0.f; }

    float4 vg[4], vu[4];   // B prefetch regs: rows {kb, kb+16} x 2 float4, g and u

    auto ldgB = [&](int kt) {
        size_t k0 = (size_t)kt * BK * FF;
#pragma unroll
        for (int i = 0; i < 2; i++) {
            const float* g = bgp + k0 + (size_t)i * 16 * FF;
            const float* u = bup + k0 + (size_t)i * 16 * FF;
            vg[i * 2 + 0] = *(const float4*)(g);
            vg[i * 2 + 1] = *(const float4*)(g + 4);
            vu[i * 2 + 0] = *(const float4*)(u);
            vu[i * 2 + 1] = *(const float4*)(u + 4);
        }
    };
    auto ldA = [&](int kt, int b) {
        uint32_t sA = sb + b * GU_STAGE;
        int k0 = kt * BK;
        cp16(sA + asoA,      arow ? (const void*)(arow + k0 + q0)     : (const void*)g_xs, arow != nullptr);
        cp16(sA + asoA + 16, arow ? (const void*)(arow + k0 + q0 + 8) : (const void*)g_xs, arow != nullptr);
    };
    auto stsB = [&](int b) {
        uint32_t sG = sb + b * GU_STAGE + A_BYTES;
        uint32_t sU = sG + B_BYTES_H;
#pragma unroll
        for (int i = 0; i < 2; i++) {
            *(uint4*)(smem + (sG - sb) + b * 0 + 0 + (size_t)(sG - sb ? 0 : 0)) ; // (no-op guard removed below)
        }
        // real stores:
#pragma unroll
        for (int i = 0; i < 2; i++) {
            *(uint4*)((char*)smem + (b * GU_STAGE + A_BYTES) + bsts[i]) = pack8(vg[i * 2], vg[i * 2 + 1]);
            *(uint4*)((char*)smem + (b * GU_STAGE + A_BYTES + B_BYTES_H) + bsts[i]) = pack8(vu[i * 2], vu[i * 2 + 1]);
        }
    };

    // prologue: fill stage 0 into buf 0
    ldgB(0);
    ldA(0, 0); CP_COMMIT();
    stsB(0);
    CP_WAIT0();
    __syncthreads();

    for (int kt = 0; kt < NKT; kt++) {
        int b = kt & 1;
        bool pre = (kt + 1 < NKT);
        if (pre) {
            ldgB(kt + 1);
            ldA(kt + 1, b ^ 1); CP_COMMIT();
        }
        // ---- compute stage kt from buf[b] ----
        uint32_t sA = sb + b * GU_STAGE;
        uint32_t sG = sA + A_BYTES;
        uint32_t sU = sG + B_BYTES_H;
        uint32_t abase = sA + a_lm;
        uint32_t gbase = sG + b_lm;
        uint32_t ubase = sU + b_lm;
#pragma unroll
        for (int kk = 0; kk < 2; kk++) {
            int kr = kk * 16;
            uint32_t af[4][4];
#pragma unroll
            for (int mt = 0; mt < 4; mt++)
                ldsm4(af[mt], abase + (uint32_t)((mt * 16 * A_STRIDE_H + kr) * 2));
            uint32_t bg[2][4], bu[2][4];
#pragma unroll
            for (int p = 0; p < 2; p++) {
                ldsm4t(bg[p], gbase + (uint32_t)((kr * B_STRIDE_H + p * 16) * 2));
                ldsm4t(bu[p], ubase + (uint32_t)((kr * B_STRIDE_H + p * 16) * 2));
            }
#pragma unroll
            for (int p = 0; p < 2; p++)
#pragma unroll
                for (int mt = 0; mt < 4; mt++) {
                    mma16(accg[mt][2 * p + 0], af[mt], bg[p][0], bg[p][1]);
                    mma16(accg[mt][2 * p + 1], af[mt], bg[p][2], bg[p][3]);
                    mma16(accu[mt][2 * p + 0], af[mt], bu[p][0], bu[p][1]);
                    mma16(accu[mt][2 * p + 1], af[mt], bu[p][2], bu[p][3]);
                }
        }
        if (pre) {
            stsB(b ^ 1);
            CP_WAIT0();
        }
        __syncthreads();
    }

    // ---- epilogue: h = fp16(silu(g) * u) ----
#pragma unroll
    for (int mt = 0; mt < 4; mt++) {
        int row0 = m0 + wm * 64 + mt * 16 + grp;
#pragma unroll
        for (int half = 0; half < 2; half++) {
            int r = row0 + half * 8;
            if (r < Mcnt) {
                __half* orow = Hout + (size_t)(base + r) * FF + n0 + wn * 32;
#pragma unroll
                for (int nt = 0; nt < 4; nt++) {
                    float gx = accg[mt][nt][half * 2 + 0];
                    float gy = accg[mt][nt][half * 2 + 1];
                    float hx = gx / (1.f + expf(-gx)) * accu[mt][nt][half * 2 + 0];
                    float hy = gy / (1.f + expf(-gy)) * accu[mt][nt][half * 2 + 1];
                    *(__half2*)(orow + nt * 8 + tg * 2) = __floats2half2_rn(hx, hy);
                }
            }
        }
    }
}

// ================= down GEMM (fp16 mma, fused weight convert) =================
template<int MODE>   // 0: routed scatter-overwrite, 1: shared accumulate
__global__ void __launch_bounds__(256) down_mma(const float* __restrict__ W_all,
                                                float* __restrict__ Out) {
    int e    = (MODE == 0) ? blockIdx.z : 0;
    int Mcnt = (MODE == 0) ? g_counts[e] : T;
    int base = (MODE == 0) ? g_offsets[e] : 0;
    int m0 = blockIdx.y * BM;
    if (m0 >= Mcnt) return;
    int n0 = blockIdx.x * BN;
    const __half* A = (MODE == 0) ? g_h : g_hs;
    const float* W = W_all + (size_t)e * FF * DM;

    extern __shared__ char smem[];
    uint32_t sb = smem_u32(smem);
    int tid = threadIdx.x, wid = tid >> 5, lane = tid & 31;
    int wm = wid >> 2, wn = wid & 3;
    int grp = lane >> 2, tg = lane & 3;

    uint32_t a_lm = (uint32_t)((((lane & 15) + wm * 64) * A_STRIDE_H + (lane >> 4) * 8) * 2);
    uint32_t b_lm = (uint32_t)(((((lane & 7) + ((lane >> 3) & 1) * 8) * B_STRIDE_H)
                               + wn * 32 + (lane >> 4) * 8) * 2);

    const __half* arow = nullptr;
    uint32_t asoA;
    int q0 = (tid & 1) * 16;
    {
        int r = tid >> 1;
        int gr = m0 + r;
        if (gr < Mcnt) arow = A + (size_t)(base + gr) * FF;
        asoA = (uint32_t)((r * A_STRIDE_H + q0) * 2);
    }
    int n8 = tid & 15, kb = tid >> 4;
    const float* wp = W + (size_t)kb * DM + n0 + n8 * 8;
    uint32_t bsts[2];
#pragma unroll
    for (int i = 0; i < 2; i++)
        bsts[i] = (uint32_t)(((kb + i * 16) * B_STRIDE_H + n8 * 8) * 2);

    float acc[4][4][4];
#pragma unroll
    for (int mt = 0; mt < 4; mt++)
#pragma unroll
        for (int nt = 0; nt < 4; nt++)
#pragma unroll
            for (int c = 0; c < 4; c++) acc[mt][nt][c] = 0.f;

    float4 vw[4];

    auto ldgB = [&](int kt) {
        size_t k0 = (size_t)kt * BK * DM;
#pragma unroll
        for (int i = 0; i < 2; i++) {
            const float* w = wp + k0 + (size_t)i * 16 * DM;
            vw[i * 2 + 0] = *(const float4*)(w);
            vw[i * 2 + 1] = *(const float4*)(w + 4);
        }
    };
    auto ldA = [&](int kt, int b) {
        uint32_t sA = sb + b * DN_STAGE;
        int k0 = kt * BK;
        cp16(sA + asoA,      arow ? (const void*)(arow + k0 + q0)     : (const void*)g_h, arow != nullptr);
        cp16(sA + asoA + 16, arow ? (const void*)(arow + k0 + q0 + 8) : (const void*)g_h, arow != nullptr);
    };
    auto stsB = [&](int b) {
#pragma unroll
        for (int i = 0; i < 2; i++)
            *(uint4*)((char*)smem + (b * DN_STAGE + A_BYTES) + bsts[i]) = pack8(vw[i * 2], vw[i * 2 + 1]);
    };

    ldgB(0);
    ldA(0, 0); CP_COMMIT();
    stsB(0);
    CP_WAIT0();
    __syncthreads();

    for (int kt = 0; kt < NKT; kt++) {
        int b = kt & 1;
        bool pre = (kt + 1 < NKT);
        if (pre) {
            ldgB(kt + 1);
            ldA(kt + 1, b ^ 1); CP_COMMIT();
        }
        uint32_t sA = sb + b * DN_STAGE;
        uint32_t sB = sA + A_BYTES;
        uint32_t abase = sA + a_lm;
        uint32_t bbase = sB + b_lm;
#pragma unroll
        for (int kk = 0; kk < 2; kk++) {
            int kr = kk * 16;
            uint32_t af[4][4];
#pragma unroll
            for (int mt = 0; mt < 4; mt++)
                ldsm4(af[mt], abase + (uint32_t)((mt * 16 * A_STRIDE_H + kr) * 2));
            uint32_t bf[2][4];
#pragma unroll
            for (int p = 0; p < 2; p++)
                ldsm4t(bf[p], bbase + (uint32_t)((kr * B_STRIDE_H + p * 16) * 2));
#pragma unroll
            for (int p = 0; p < 2; p++)
#pragma unroll
                for (int mt = 0; mt < 4; mt++) {
                    mma16(acc[mt][2 * p + 0], af[mt], bf[p][0], bf[p][1]);
                    mma16(acc[mt][2 * p + 1], af[mt], bf[p][2], bf[p][3]);
                }
        }
        if (pre) {
            stsB(b ^ 1);
            CP_WAIT0();
        }
        __syncthreads();
    }

    // ---- epilogue ----
#pragma unroll
    for (int mt = 0; mt < 4; mt++) {
        int row0 = m0 + wm * 64 + mt * 16 + grp;
#pragma unroll
        for (int half = 0; half < 2; half++) {
            int r = row0 + half * 8;
            if (r < Mcnt) {
                int tok = (MODE == 0) ? g_perm[base + r] : r;
                float* orow = Out + (size_t)tok * DM + n0 + wn * 32;
#pragma unroll
                for (int nt = 0; nt < 4; nt++) {
                    float vx = acc[mt][nt][half * 2 + 0];
                    float vy = acc[mt][nt][half * 2 + 1];
                    float* o = orow + nt * 8 + tg * 2;
                    if (MODE == 0) {
                        *(float2*)o = make_float2(vx, vy);
                    } else {
                        float2 p = *(const float2*)o;
                        *(float2*)o = make_float2(p.x + vx, p.y + vy);
                    }
                }
            }
        }
    }
}

// ---------------- launch ----------------
extern "C" void kernel_launch(void* const* d_in, const int* in_sizes, int n_in,
                              void* d_out, int out_size) {
    const float* hidden   = (const float*)d_in[0];
    const float* router_w = (const float*)d_in[1];
    const float* gate_w   = (const float*)d_in[2];
    const float* up_w     = (const float*)d_in[3];
    const float* down_w   = (const float*)d_in[4];
    const float* sgate    = (const float*)d_in[5];
    const float* sup      = (const float*)d_in[6];
    const float* sdown    = (const float*)d_in[7];
    float* out = (float*)d_out;

    cudaFuncSetAttribute(gateup_mma,  cudaFuncAttributeMaxDynamicSharedMemorySize, GU_SMEM);
    cudaFuncSetAttribute(down_mma<0>, cudaFuncAttributeMaxDynamicSharedMemorySize, DN_SMEM);
    cudaFuncSetAttribute(down_mma<1>, cudaFuncAttributeMaxDynamicSharedMemorySize, DN_SMEM);

    init_kernel<<<1, 32>>>();
    router_kernel<<<T, 256>>>(hidden, router_w);
    scan_kernel<<<1, 32>>>();
    scatter_kernel<<<T / 256, 256>>>();

    dim3 gg(FF / BN, T / BM, NE + 1);   // z: 0..7 routed experts, 8 = shared expert
    gateup_mma<<<gg, 256, GU_SMEM>>>(gate_w, up_w, sgate, sup);

    dim3 dr(DM / BN, T / BM, NE);
    dim3 ds(DM / BN, T / BM, 1);
    down_mma<0><<<dr, 256, DN_SMEM>>>(down_w, out);    // scatter-overwrite (covers all tokens)
    down_mma<1><<<ds, 256, DN_SMEM>>>(sdown, out);     // accumulate shared expert
}